// round 13
// baseline (speedup 1.0000x reference)
#include <cuda_runtime.h>
#include <cuda_fp16.h>
#include <cstdint>
#include <math_constants.h>

#define NN 50000
#define NE 800000
#define IND 512
#define HID 64
#define OUTD 40
#define CAP 96    // max degree slots per node; Poisson(16) -> P(>96) ~ 0

#define NBF 782   // fill blocks: NE/4/256 rounded up
#define NBG 391   // gemm1 blocks: NN/128 rounded up

typedef unsigned long long u64;

// ---------------- scratch (static device arrays; no allocation) -------------
__device__ int            g_cnt[NN];
__device__ float          g_disw[NN];                        // rsqrt(cnt+1)
__device__ unsigned short g_slot[(size_t)NN * CAP];          // src ids per dst node
__device__ __align__(16) __half g_hs1h[(size_t)NN * HID];    // raw (x@W1), fp16
__device__ __align__(16) float  g_h[(size_t)NN * HID];       // relu(d*agg+b), PRE-dropout
__device__ __align__(16) __half g_hs2h[(size_t)NN * 64];     // d*(h@W2), fp16, padded 64/row

// ---------------- packed f32x2 helpers (sm_100a) ------------------------------
__device__ __forceinline__ u64 f2_pack(float lo, float hi) {
    u64 r; asm("mov.b64 %0,{%1,%2};" : "=l"(r) : "f"(lo), "f"(hi)); return r;
}
__device__ __forceinline__ void f2_unpack(u64 v, float& lo, float& hi) {
    asm("mov.b64 {%0,%1},%2;" : "=f"(lo), "=f"(hi) : "l"(v));
}
__device__ __forceinline__ u64 f2_add(u64 a, u64 b) {
    u64 r; asm("add.rn.f32x2 %0,%1,%2;" : "=l"(r) : "l"(a), "l"(b)); return r;
}
__device__ __forceinline__ u64 f2_fma(u64 a, u64 b, u64 c) {
    u64 r; asm("fma.rn.f32x2 %0,%1,%2,%3;" : "=l"(r) : "l"(a), "l"(b), "l"(c)); return r;
}
__device__ __forceinline__ u64 h2_to_f2(uint32_t h) {
    float2 f = __half22float2(*reinterpret_cast<__half2*>(&h));
    return f2_pack(f.x, f.y);
}

// ---------------- GEMM1 helpers (TF32 tensor cores) --------------------------
__device__ __forceinline__ uint32_t f2tf32(float f) {
    uint32_t r;
    asm("cvt.rna.tf32.f32 %0, %1;" : "=r"(r) : "f"(f));
    return r;
}

__device__ __forceinline__ void mma_tf32(float* c, const uint32_t* a, const uint32_t* b) {
    asm volatile(
        "mma.sync.aligned.m16n8k8.row.col.f32.tf32.tf32.f32 "
        "{%0,%1,%2,%3}, {%4,%5,%6,%7}, {%8,%9}, {%0,%1,%2,%3};"
        : "+f"(c[0]), "+f"(c[1]), "+f"(c[2]), "+f"(c[3])
        : "r"(a[0]), "r"(a[1]), "r"(a[2]), "r"(a[3]), "r"(b[0]), "r"(b[1]));
}

#define XPAD 36
#define WPAD 72

// ---------------- fused: slot fill (blocks < NBF)  ∥  GEMM1 (rest) ----------
__global__ __launch_bounds__(256) void k_fill_gemm1(const int* __restrict__ src,
                                                    const int* __restrict__ dst,
                                                    const float* __restrict__ x,
                                                    const float* __restrict__ W1) {
    __shared__ uint32_t xs[128][XPAD];
    __shared__ uint32_t ws[32][WPAD];

    if (blockIdx.x < NBF) {   // ---- direct slot fill ----
        int i = (blockIdx.x * 256 + threadIdx.x) * 4;
        if (i < NE) {
            int4 s4 = *(const int4*)(src + i);
            int4 d4 = *(const int4*)(dst + i);
            int p0 = atomicAdd(&g_cnt[d4.x], 1);
            int p1 = atomicAdd(&g_cnt[d4.y], 1);
            int p2 = atomicAdd(&g_cnt[d4.z], 1);
            int p3 = atomicAdd(&g_cnt[d4.w], 1);
            if (p0 < CAP) g_slot[(size_t)d4.x * CAP + p0] = (unsigned short)s4.x;
            if (p1 < CAP) g_slot[(size_t)d4.y * CAP + p1] = (unsigned short)s4.y;
            if (p2 < CAP) g_slot[(size_t)d4.z * CAP + p2] = (unsigned short)s4.z;
            if (p3 < CAP) g_slot[(size_t)d4.w * CAP + p3] = (unsigned short)s4.w;
        }
        return;
    }

    // ---- GEMM1 path: hs1 = x @ W1 (raw), register prefetch on x ----
    const int row0 = (blockIdx.x - NBF) * 128;
    const int t = threadIdx.x;
    const int wid = t >> 5, lane = t & 31;
    const int wm = wid >> 1, wn = wid & 1;
    const int g = lane >> 2, tig = lane & 3;

    int xr_r[4], xr_q[4];
    bool xr_ok[4];
#pragma unroll
    for (int i = 0; i < 4; i++) {
        int f = t + 256 * i;
        xr_r[i] = f >> 3;
        xr_q[i] = (f & 7) << 2;
        xr_ok[i] = (row0 + xr_r[i]) < NN;
    }

    float4 xr[4];
#pragma unroll
    for (int i = 0; i < 4; i++) {
        xr[i] = make_float4(0.f, 0.f, 0.f, 0.f);
        if (xr_ok[i]) xr[i] = *(const float4*)(x + (size_t)(row0 + xr_r[i]) * IND + xr_q[i]);
    }

    float acc[2][4][4] = {};

    for (int kb = 0; kb < IND; kb += 32) {
#pragma unroll
        for (int i = 0; i < 4; i++) {
            int r = xr_r[i], q = xr_q[i];
            xs[r][q]     = f2tf32(xr[i].x);
            xs[r][q + 1] = f2tf32(xr[i].y);
            xs[r][q + 2] = f2tf32(xr[i].z);
            xs[r][q + 3] = f2tf32(xr[i].w);
        }
#pragma unroll
        for (int i = 0; i < 2; i++) {
            int f = t + 256 * i;
            int kk = f >> 4, c4 = (f & 15) << 2;
            float4 v = *(const float4*)(W1 + (size_t)(kb + kk) * HID + c4);
            ws[kk][c4]     = f2tf32(v.x);
            ws[kk][c4 + 1] = f2tf32(v.y);
            ws[kk][c4 + 2] = f2tf32(v.z);
            ws[kk][c4 + 3] = f2tf32(v.w);
        }
        __syncthreads();

        if (kb + 32 < IND) {
#pragma unroll
            for (int i = 0; i < 4; i++)
                if (xr_ok[i])
                    xr[i] = *(const float4*)(x + (size_t)(row0 + xr_r[i]) * IND + (kb + 32) + xr_q[i]);
        }

#pragma unroll
        for (int k8 = 0; k8 < 4; k8++) {
            int k0 = k8 * 8;
            uint32_t a[2][4], b[4][2];
#pragma unroll
            for (int i = 0; i < 2; i++) {
                int rb = wm * 32 + i * 16;
                a[i][0] = xs[rb + g][k0 + tig];
                a[i][1] = xs[rb + g + 8][k0 + tig];
                a[i][2] = xs[rb + g][k0 + tig + 4];
                a[i][3] = xs[rb + g + 8][k0 + tig + 4];
            }
#pragma unroll
            for (int j = 0; j < 4; j++) {
                int nb = wn * 32 + j * 8 + g;
                b[j][0] = ws[k0 + tig][nb];
                b[j][1] = ws[k0 + tig + 4][nb];
            }
#pragma unroll
            for (int i = 0; i < 2; i++)
#pragma unroll
                for (int j = 0; j < 4; j++)
                    mma_tf32(acc[i][j], a[i], b[j]);
        }
        __syncthreads();
    }

    // epilogue: store fp16 (adjacent col pairs -> one half2)
#pragma unroll
    for (int i = 0; i < 2; i++) {
        int r_lo = row0 + wm * 32 + i * 16 + g;
        int r_hi = r_lo + 8;
#pragma unroll
        for (int j = 0; j < 4; j++) {
            int c = wn * 32 + j * 8 + 2 * tig;
            if (r_lo < NN)
                *(__half2*)(g_hs1h + (unsigned)(r_lo * HID + c)) =
                    __floats2half2_rn(acc[i][j][0], acc[i][j][1]);
            if (r_hi < NN)
                *(__half2*)(g_hs1h + (unsigned)(r_hi * HID + c)) =
                    __floats2half2_rn(acc[i][j][2], acc[i][j][3]);
        }
    }
}

// ---------------- dis precompute ---------------------------------------------
__global__ void k_dis() {
    int i = blockIdx.x * blockDim.x + threadIdx.x;
    if (i < NN) g_disw[i] = rsqrtf((float)(g_cnt[i] + 1));
}

// ---------------- threefry2x32 (JAX partitionable), key (0, 42) -------------
__device__ __forceinline__ uint32_t rotl32(uint32_t x, int r) {
    return (x << r) | (x >> (32 - r));
}

__device__ __forceinline__ uint32_t tf_bits(uint32_t i) {
    uint32_t x0 = 0u, x1 = i;
    const uint32_t k0 = 0u, k1 = 42u, k2 = 0x1BD11BDAu ^ 42u;
    x0 += k0; x1 += k1;
#define TF_ROUND(r) { x0 += x1; x1 = rotl32(x1, r); x1 ^= x0; }
    TF_ROUND(13) TF_ROUND(15) TF_ROUND(26) TF_ROUND(6)
    x0 += k1; x1 += k2 + 1u;
    TF_ROUND(17) TF_ROUND(29) TF_ROUND(16) TF_ROUND(24)
    x0 += k2; x1 += k0 + 2u;
    TF_ROUND(13) TF_ROUND(15) TF_ROUND(26) TF_ROUND(6)
    x0 += k0; x1 += k1 + 3u;
    TF_ROUND(17) TF_ROUND(29) TF_ROUND(16) TF_ROUND(24)
    x0 += k1; x1 += k2 + 4u;
    TF_ROUND(13) TF_ROUND(15) TF_ROUND(26) TF_ROUND(6)
    x0 += k2; x1 += k0 + 5u;
#undef TF_ROUND
    return x0 ^ x1;
}

// ---------------- agg1: warp/node, 8 chunk-lanes x 4 slots, unroll 3 --------
// hs1 row = 64 half = 128B = 8 uint4; packed f32x2 FMA; dis from g_disw
__global__ void k_agg1(const float* __restrict__ b1) {
    int node = blockIdx.x * (blockDim.x >> 5) + (threadIdx.x >> 5);
    if (node >= NN) return;
    int lane = threadIdx.x & 31;
    int c8 = lane & 7, p = lane >> 3;           // chunk, slot
    const uint4* hv = (const uint4*)g_hs1h;     // row stride 8 uint4

    int deg = g_cnt[node];
    float dn = g_disw[node];
    const unsigned short* sl = g_slot + (unsigned)node * CAP;

    u64 acc0 = 0, acc1 = 0, acc2 = 0, acc3 = 0;   // 8 fp32 lanes packed
    if (p == 0) {   // self-loop
        uint4 r = hv[(unsigned)(node * 8 + c8)];
        u64 dw = f2_pack(dn, dn);
        acc0 = f2_fma(h2_to_f2(r.x), dw, acc0);
        acc1 = f2_fma(h2_to_f2(r.y), dw, acc1);
        acc2 = f2_fma(h2_to_f2(r.z), dw, acc2);
        acc3 = f2_fma(h2_to_f2(r.w), dw, acc3);
    }

#define A1_STEP(KK) {                                                    \
        int s_ = sl[KK];                                                 \
        float w_ = __ldg(&g_disw[s_]);                                   \
        u64 ww_ = f2_pack(w_, w_);                                       \
        uint4 v_ = hv[(unsigned)(s_ * 8 + c8)];                          \
        acc0 = f2_fma(h2_to_f2(v_.x), ww_, acc0);                        \
        acc1 = f2_fma(h2_to_f2(v_.y), ww_, acc1);                        \
        acc2 = f2_fma(h2_to_f2(v_.z), ww_, acc2);                        \
        acc3 = f2_fma(h2_to_f2(v_.w), ww_, acc3); }

    int k = p;
    for (; k + 8 < deg; k += 12) {   // 3 rows in flight per slot x 4 slots
        A1_STEP(k) A1_STEP(k + 4) A1_STEP(k + 8)
    }
    for (; k < deg; k += 4) A1_STEP(k)
#undef A1_STEP

    // unpack and combine 4 slots -> lanes 0..7
    float f[8];
    f2_unpack(acc0, f[0], f[1]);
    f2_unpack(acc1, f[2], f[3]);
    f2_unpack(acc2, f[4], f[5]);
    f2_unpack(acc3, f[6], f[7]);
#pragma unroll
    for (int i = 0; i < 8; i++) f[i] += __shfl_down_sync(0xFFFFFFFFu, f[i], 16);
#pragma unroll
    for (int i = 0; i < 8; i++) f[i] += __shfl_down_sync(0xFFFFFFFFu, f[i], 8);

    if (p == 0) {   // lanes 0..7: bias + relu, store fp32 (pre-dropout)
        float4 b0 = ((const float4*)b1)[c8 * 2];
        float4 b2v = ((const float4*)b1)[c8 * 2 + 1];
        float4 v0, v1;
        v0.x = fmaxf(fmaf(dn, f[0], b0.x), 0.f);
        v0.y = fmaxf(fmaf(dn, f[1], b0.y), 0.f);
        v0.z = fmaxf(fmaf(dn, f[2], b0.z), 0.f);
        v0.w = fmaxf(fmaf(dn, f[3], b0.w), 0.f);
        v1.x = fmaxf(fmaf(dn, f[4], b2v.x), 0.f);
        v1.y = fmaxf(fmaf(dn, f[5], b2v.y), 0.f);
        v1.z = fmaxf(fmaf(dn, f[6], b2v.z), 0.f);
        v1.w = fmaxf(fmaf(dn, f[7], b2v.w), 0.f);
        ((float4*)g_h)[(unsigned)(node * 16 + c8 * 2)]     = v0;
        ((float4*)g_h)[(unsigned)(node * 16 + c8 * 2 + 1)] = v1;
    }
}

// ---------------- GEMM2: hs2 = dis .* (dropout(h) @ W2), fp16 out -----------
__global__ void k_gemm2(const float* __restrict__ W2) {
    __shared__ float hsm[64][65];
    __shared__ float w2s[64][OUTD];
    const int row0 = blockIdx.x * 64;
    const int t = threadIdx.x;

    for (int idx = t; idx < 64 * 64; idx += 320) {
        int r = idx >> 6, k = idx & 63;
        int gr = row0 + r;
        float val = 0.f;
        if (gr < NN) {
            uint32_t i0 = (uint32_t)gr * HID + k;
            val = g_h[i0];
            val = (tf_bits(i0) < 0x80000000u) ? val * 2.0f : 0.f;   // dropout here
        }
        hsm[r][k] = val;
    }
    for (int idx = t; idx < 64 * OUTD; idx += 320)
        w2s[idx / OUTD][idx % OUTD] = W2[idx];
    __syncthreads();

    int r8 = t / OUTD;
    int c = t % OUTD;
    float acc[8] = {};
#pragma unroll
    for (int k = 0; k < 64; k++) {
        float b = w2s[k][c];
#pragma unroll
        for (int i = 0; i < 8; i++)
            acc[i] = fmaf(hsm[r8 * 8 + i][k], b, acc[i]);
    }
#pragma unroll
    for (int i = 0; i < 8; i++) {
        int row = row0 + r8 * 8 + i;
        if (row < NN) {
            float d = __ldg(&g_disw[row]);
            g_hs2h[(unsigned)(row * 64 + c)] = __float2half(d * acc[i]);
        }
    }
}

// ---------------- agg2: warp/node, 10 chunk-lanes x 3 slots, unroll 4 -------
// hs2 row = 64 half padded = 128B = 16 uint2; packed f32x2 adds
__global__ void k_agg2(const float* __restrict__ b2, float* __restrict__ out) {
    int node = blockIdx.x * (blockDim.x >> 5) + (threadIdx.x >> 5);
    if (node >= NN) return;
    int lane = threadIdx.x & 31;
    int c = lane % 10;
    int p = (lane < 30) ? (lane / 10) : 3;     // slots 0..2; lanes 30,31 idle
    const uint2* hv = (const uint2*)g_hs2h;    // row stride 16 uint2; use first 10

    int deg = g_cnt[node];
    const unsigned short* sl = g_slot + (unsigned)node * CAP;

    u64 acc0 = 0, acc1 = 0;
    if (lane < 10) {   // self-loop
        uint2 r = hv[(unsigned)(node * 16 + c)];
        acc0 = h2_to_f2(r.x);
        acc1 = h2_to_f2(r.y);
    }

#define A2_STEP(KK) {                                           \
        int s_ = sl[KK];                                        \
        uint2 v_ = hv[(unsigned)(s_ * 16 + c)];                 \
        acc0 = f2_add(acc0, h2_to_f2(v_.x));                    \
        acc1 = f2_add(acc1, h2_to_f2(v_.y)); }

    if (p < 3) {
        int k = p;
        for (; k + 9 < deg; k += 12) {   // 4 rows in flight per slot x 3 slots
            A2_STEP(k) A2_STEP(k + 3) A2_STEP(k + 6) A2_STEP(k + 9)
        }
        for (; k < deg; k += 3) A2_STEP(k)
    }
#undef A2_STEP

    float ax, ay, az, aw;
    f2_unpack(acc0, ax, ay);
    f2_unpack(acc1, az, aw);

    float rx = ax + __shfl_down_sync(0xFFFFFFFFu, ax, 10) + __shfl_down_sync(0xFFFFFFFFu, ax, 20);
    float ry = ay + __shfl_down_sync(0xFFFFFFFFu, ay, 10) + __shfl_down_sync(0xFFFFFFFFu, ay, 20);
    float rz = az + __shfl_down_sync(0xFFFFFFFFu, az, 10) + __shfl_down_sync(0xFFFFFFFFu, az, 20);
    float rw = aw + __shfl_down_sync(0xFFFFFFFFu, aw, 10) + __shfl_down_sync(0xFFFFFFFFu, aw, 20);

    float4 v = make_float4(-CUDART_INF_F, -CUDART_INF_F, -CUDART_INF_F, -CUDART_INF_F);
    if (lane < 10) {
        float d = g_disw[node];
        float4 bb = ((const float4*)b2)[c];
        v.x = fmaf(d, rx, bb.x);
        v.y = fmaf(d, ry, bb.y);
        v.z = fmaf(d, rz, bb.z);
        v.w = fmaf(d, rw, bb.w);
    }
    float m = fmaxf(fmaxf(v.x, v.y), fmaxf(v.z, v.w));
#pragma unroll
    for (int o = 16; o; o >>= 1) m = fmaxf(m, __shfl_xor_sync(0xFFFFFFFFu, m, o));
    float s = 0.f;
    if (lane < 10)
        s = expf(v.x - m) + expf(v.y - m) + expf(v.z - m) + expf(v.w - m);
#pragma unroll
    for (int o = 16; o; o >>= 1) s += __shfl_xor_sync(0xFFFFFFFFu, s, o);
    float lse = m + logf(s);

    if (lane < 10) {
        float4 o4 = make_float4(v.x - lse, v.y - lse, v.z - lse, v.w - lse);
        ((float4*)out)[(unsigned)(node * 10 + c)] = o4;
    }
}

// ---------------- launch -----------------------------------------------------
extern "C" void kernel_launch(void* const* d_in, const int* in_sizes, int n_in,
                              void* d_out, int out_size) {
    const float* x  = (const float*)d_in[0];
    const int*   ei = (const int*)d_in[1];     // [2, NE] row-major
    const float* W1 = (const float*)d_in[2];
    const float* b1 = (const float*)d_in[3];
    const float* W2 = (const float*)d_in[4];
    const float* b2 = (const float*)d_in[5];
    float* out = (float*)d_out;
    const int* src = ei;
    const int* dst = ei + NE;

    void* cnt_ptr = nullptr;
    cudaGetSymbolAddress(&cnt_ptr, g_cnt);
    cudaMemsetAsync(cnt_ptr, 0, NN * sizeof(int));

    k_fill_gemm1<<<NBF + NBG, 256>>>(src, dst, x, W1);   // slot fill ∥ GEMM1
    k_dis<<<(NN + 255) / 256, 256>>>();
    k_agg1<<<(NN * 32 + 255) / 256, 256>>>(b1);
    k_gemm2<<<(NN + 63) / 64, 320>>>(W2);
    k_agg2<<<(NN * 32 + 255) / 256, 256>>>(b2, out);
}

// round 14
// speedup vs baseline: 1.0468x; 1.0468x over previous
#include <cuda_runtime.h>
#include <cuda_fp16.h>
#include <cstdint>
#include <math_constants.h>

#define NN 50000
#define NE 800000
#define IND 512
#define HID 64
#define OUTD 40
#define CAP 96    // max degree slots per node; Poisson(16) -> P(>96) ~ 0

#define NBF 782   // fill blocks: NE/4/256 rounded up
#define NBG 391   // gemm1 blocks: NN/128 rounded up
#define NMASK ((NN * HID) / 32)   // 100000 mask words
#define NBM 391   // mask blocks: NMASK/256 rounded up

// ---------------- scratch (static device arrays; no allocation) -------------
__device__ int            g_cnt[NN];
__device__ unsigned short g_slot[(size_t)NN * CAP];          // src ids per dst node
__device__ uint32_t       g_mask[NMASK];                     // dropout keep bits
__device__ __align__(16) __half g_hs1h[(size_t)NN * HID];    // raw (x@W1), fp16
__device__ __align__(16) float  g_h[(size_t)NN * HID];       // post relu+dropout
__device__ __align__(16) __half g_hs2h[(size_t)NN * 64];     // d*(h@W2), fp16, padded 64/row

// ---------------- threefry2x32 (JAX partitionable), key (0, 42) -------------
__device__ __forceinline__ uint32_t rotl32(uint32_t x, int r) {
    return (x << r) | (x >> (32 - r));
}

__device__ __forceinline__ uint32_t tf_bits(uint32_t i) {
    uint32_t x0 = 0u, x1 = i;
    const uint32_t k0 = 0u, k1 = 42u, k2 = 0x1BD11BDAu ^ 42u;
    x0 += k0; x1 += k1;
#define TF_ROUND(r) { x0 += x1; x1 = rotl32(x1, r); x1 ^= x0; }
    TF_ROUND(13) TF_ROUND(15) TF_ROUND(26) TF_ROUND(6)
    x0 += k1; x1 += k2 + 1u;
    TF_ROUND(17) TF_ROUND(29) TF_ROUND(16) TF_ROUND(24)
    x0 += k2; x1 += k0 + 2u;
    TF_ROUND(13) TF_ROUND(15) TF_ROUND(26) TF_ROUND(6)
    x0 += k0; x1 += k1 + 3u;
    TF_ROUND(17) TF_ROUND(29) TF_ROUND(16) TF_ROUND(24)
    x0 += k1; x1 += k2 + 4u;
    TF_ROUND(13) TF_ROUND(15) TF_ROUND(26) TF_ROUND(6)
    x0 += k2; x1 += k0 + 5u;
#undef TF_ROUND
    return x0 ^ x1;
}

// ---------------- GEMM1 helpers (TF32 tensor cores) --------------------------
__device__ __forceinline__ uint32_t f2tf32(float f) {
    uint32_t r;
    asm("cvt.rna.tf32.f32 %0, %1;" : "=r"(r) : "f"(f));
    return r;
}

__device__ __forceinline__ void mma_tf32(float* c, const uint32_t* a, const uint32_t* b) {
    asm volatile(
        "mma.sync.aligned.m16n8k8.row.col.f32.tf32.tf32.f32 "
        "{%0,%1,%2,%3}, {%4,%5,%6,%7}, {%8,%9}, {%0,%1,%2,%3};"
        : "+f"(c[0]), "+f"(c[1]), "+f"(c[2]), "+f"(c[3])
        : "r"(a[0]), "r"(a[1]), "r"(a[2]), "r"(a[3]), "r"(b[0]), "r"(b[1]));
}

#define XPAD 36
#define WPAD 72

// ------- fused: slot fill (< NBF) ∥ GEMM1 (< NBF+NBG) ∥ dropout mask (rest) --
__global__ __launch_bounds__(256) void k_fill_gemm1(const int* __restrict__ src,
                                                    const int* __restrict__ dst,
                                                    const float* __restrict__ x,
                                                    const float* __restrict__ W1) {
    __shared__ uint32_t xs[128][XPAD];
    __shared__ uint32_t ws[32][WPAD];

    if (blockIdx.x < NBF) {   // ---- direct slot fill ----
        int i = (blockIdx.x * 256 + threadIdx.x) * 4;
        if (i < NE) {
            int4 s4 = *(const int4*)(src + i);
            int4 d4 = *(const int4*)(dst + i);
            int p0 = atomicAdd(&g_cnt[d4.x], 1);
            int p1 = atomicAdd(&g_cnt[d4.y], 1);
            int p2 = atomicAdd(&g_cnt[d4.z], 1);
            int p3 = atomicAdd(&g_cnt[d4.w], 1);
            if (p0 < CAP) g_slot[(size_t)d4.x * CAP + p0] = (unsigned short)s4.x;
            if (p1 < CAP) g_slot[(size_t)d4.y * CAP + p1] = (unsigned short)s4.y;
            if (p2 < CAP) g_slot[(size_t)d4.z * CAP + p2] = (unsigned short)s4.z;
            if (p3 < CAP) g_slot[(size_t)d4.w * CAP + p3] = (unsigned short)s4.w;
        }
        return;
    }

    if (blockIdx.x >= NBF + NBG) {   // ---- dropout mask gen (pure ALU) ----
        int j = (blockIdx.x - NBF - NBG) * 256 + threadIdx.x;
        if (j < NMASK) {
            uint32_t base = (uint32_t)j << 5;
            uint32_t w = 0;
#pragma unroll 8
            for (int b = 0; b < 32; b++)
                w |= ((tf_bits(base + b) >> 31) ^ 1u) << b;   // keep iff MSB==0
            g_mask[j] = w;
        }
        return;
    }

    // ---- GEMM1 path: hs1 = x @ W1 (raw), register prefetch on x ----
    const int row0 = (blockIdx.x - NBF) * 128;
    const int t = threadIdx.x;
    const int wid = t >> 5, lane = t & 31;
    const int wm = wid >> 1, wn = wid & 1;
    const int g = lane >> 2, tig = lane & 3;

    int xr_r[4], xr_q[4];
    bool xr_ok[4];
#pragma unroll
    for (int i = 0; i < 4; i++) {
        int f = t + 256 * i;
        xr_r[i] = f >> 3;
        xr_q[i] = (f & 7) << 2;
        xr_ok[i] = (row0 + xr_r[i]) < NN;
    }

    float4 xr[4];
#pragma unroll
    for (int i = 0; i < 4; i++) {
        xr[i] = make_float4(0.f, 0.f, 0.f, 0.f);
        if (xr_ok[i]) xr[i] = *(const float4*)(x + (size_t)(row0 + xr_r[i]) * IND + xr_q[i]);
    }

    float acc[2][4][4] = {};

    for (int kb = 0; kb < IND; kb += 32) {
#pragma unroll
        for (int i = 0; i < 4; i++) {
            int r = xr_r[i], q = xr_q[i];
            xs[r][q]     = f2tf32(xr[i].x);
            xs[r][q + 1] = f2tf32(xr[i].y);
            xs[r][q + 2] = f2tf32(xr[i].z);
            xs[r][q + 3] = f2tf32(xr[i].w);
        }
#pragma unroll
        for (int i = 0; i < 2; i++) {
            int f = t + 256 * i;
            int kk = f >> 4, c4 = (f & 15) << 2;
            float4 v = *(const float4*)(W1 + (size_t)(kb + kk) * HID + c4);
            ws[kk][c4]     = f2tf32(v.x);
            ws[kk][c4 + 1] = f2tf32(v.y);
            ws[kk][c4 + 2] = f2tf32(v.z);
            ws[kk][c4 + 3] = f2tf32(v.w);
        }
        __syncthreads();

        if (kb + 32 < IND) {
#pragma unroll
            for (int i = 0; i < 4; i++)
                if (xr_ok[i])
                    xr[i] = *(const float4*)(x + (size_t)(row0 + xr_r[i]) * IND + (kb + 32) + xr_q[i]);
        }

#pragma unroll
        for (int k8 = 0; k8 < 4; k8++) {
            int k0 = k8 * 8;
            uint32_t a[2][4], b[4][2];
#pragma unroll
            for (int i = 0; i < 2; i++) {
                int rb = wm * 32 + i * 16;
                a[i][0] = xs[rb + g][k0 + tig];
                a[i][1] = xs[rb + g + 8][k0 + tig];
                a[i][2] = xs[rb + g][k0 + tig + 4];
                a[i][3] = xs[rb + g + 8][k0 + tig + 4];
            }
#pragma unroll
            for (int j = 0; j < 4; j++) {
                int nb = wn * 32 + j * 8 + g;
                b[j][0] = ws[k0 + tig][nb];
                b[j][1] = ws[k0 + tig + 4][nb];
            }
#pragma unroll
            for (int i = 0; i < 2; i++)
#pragma unroll
                for (int j = 0; j < 4; j++)
                    mma_tf32(acc[i][j], a[i], b[j]);
        }
        __syncthreads();
    }

    // epilogue: store fp16 (adjacent col pairs -> one half2)
#pragma unroll
    for (int i = 0; i < 2; i++) {
        int r_lo = row0 + wm * 32 + i * 16 + g;
        int r_hi = r_lo + 8;
#pragma unroll
        for (int j = 0; j < 4; j++) {
            int c = wn * 32 + j * 8 + 2 * tig;
            if (r_lo < NN)
                *(__half2*)(g_hs1h + (unsigned)(r_lo * HID + c)) =
                    __floats2half2_rn(acc[i][j][0], acc[i][j][1]);
            if (r_hi < NN)
                *(__half2*)(g_hs1h + (unsigned)(r_hi * HID + c)) =
                    __floats2half2_rn(acc[i][j][2], acc[i][j][3]);
        }
    }
}

// ---------------- agg1: warp/node, 8 chunk-lanes x 4 slots, unroll 3 --------
// hs1 row = 64 half = 128B = 8 uint4; dropout applied at write via g_mask
__global__ void k_agg1(const float* __restrict__ b1) {
    int node = blockIdx.x * (blockDim.x >> 5) + (threadIdx.x >> 5);
    if (node >= NN) return;
    int lane = threadIdx.x & 31;
    int c8 = lane & 7, p = lane >> 3;           // chunk, slot
    const uint4* hv = (const uint4*)g_hs1h;     // row stride 8 uint4

    int deg = g_cnt[node];
    float dn = rsqrtf((float)(deg + 1));
    const unsigned short* sl = g_slot + (unsigned)node * CAP;

    float4 a0 = make_float4(0.f, 0.f, 0.f, 0.f);
    float4 a1 = make_float4(0.f, 0.f, 0.f, 0.f);
    if (p == 0) {   // self-loop
        uint4 r = hv[(unsigned)(node * 8 + c8)];
        float2 f0 = __half22float2(*(__half2*)&r.x);
        float2 f1 = __half22float2(*(__half2*)&r.y);
        float2 f2 = __half22float2(*(__half2*)&r.z);
        float2 f3 = __half22float2(*(__half2*)&r.w);
        a0.x = dn * f0.x; a0.y = dn * f0.y; a0.z = dn * f1.x; a0.w = dn * f1.y;
        a1.x = dn * f2.x; a1.y = dn * f2.y; a1.z = dn * f3.x; a1.w = dn * f3.y;
    }

#define A1_STEP(KK) {                                                    \
        int s_ = sl[KK];                                                 \
        float w_ = rsqrtf((float)(__ldg(&g_cnt[s_]) + 1));               \
        uint4 v_ = hv[(unsigned)(s_ * 8 + c8)];                          \
        float2 f0_ = __half22float2(*(__half2*)&v_.x);                   \
        float2 f1_ = __half22float2(*(__half2*)&v_.y);                   \
        float2 f2_ = __half22float2(*(__half2*)&v_.z);                   \
        float2 f3_ = __half22float2(*(__half2*)&v_.w);                   \
        a0.x = fmaf(w_, f0_.x, a0.x); a0.y = fmaf(w_, f0_.y, a0.y);      \
        a0.z = fmaf(w_, f1_.x, a0.z); a0.w = fmaf(w_, f1_.y, a0.w);      \
        a1.x = fmaf(w_, f2_.x, a1.x); a1.y = fmaf(w_, f2_.y, a1.y);      \
        a1.z = fmaf(w_, f3_.x, a1.z); a1.w = fmaf(w_, f3_.y, a1.w); }

    int k = p;
    for (; k + 8 < deg; k += 12) {   // 3 rows in flight per slot x 4 slots
        A1_STEP(k) A1_STEP(k + 4) A1_STEP(k + 8)
    }
    for (; k < deg; k += 4) A1_STEP(k)
#undef A1_STEP

    // combine 4 slots -> lanes 0..7
    a0.x += __shfl_down_sync(0xFFFFFFFFu, a0.x, 16);
    a0.y += __shfl_down_sync(0xFFFFFFFFu, a0.y, 16);
    a0.z += __shfl_down_sync(0xFFFFFFFFu, a0.z, 16);
    a0.w += __shfl_down_sync(0xFFFFFFFFu, a0.w, 16);
    a1.x += __shfl_down_sync(0xFFFFFFFFu, a1.x, 16);
    a1.y += __shfl_down_sync(0xFFFFFFFFu, a1.y, 16);
    a1.z += __shfl_down_sync(0xFFFFFFFFu, a1.z, 16);
    a1.w += __shfl_down_sync(0xFFFFFFFFu, a1.w, 16);
    a0.x += __shfl_down_sync(0xFFFFFFFFu, a0.x, 8);
    a0.y += __shfl_down_sync(0xFFFFFFFFu, a0.y, 8);
    a0.z += __shfl_down_sync(0xFFFFFFFFu, a0.z, 8);
    a0.w += __shfl_down_sync(0xFFFFFFFFu, a0.w, 8);
    a1.x += __shfl_down_sync(0xFFFFFFFFu, a1.x, 8);
    a1.y += __shfl_down_sync(0xFFFFFFFFu, a1.y, 8);
    a1.z += __shfl_down_sync(0xFFFFFFFFu, a1.z, 8);
    a1.w += __shfl_down_sync(0xFFFFFFFFu, a1.w, 8);

    if (p == 0) {   // lanes 0..7: bias + relu + dropout (mask bits), store fp32
        float4 b0 = ((const float4*)b1)[c8 * 2];
        float4 b2v = ((const float4*)b1)[c8 * 2 + 1];
        float4 v0, v1;
        v0.x = fmaxf(fmaf(dn, a0.x, b0.x), 0.f);
        v0.y = fmaxf(fmaf(dn, a0.y, b0.y), 0.f);
        v0.z = fmaxf(fmaf(dn, a0.z, b0.z), 0.f);
        v0.w = fmaxf(fmaf(dn, a0.w, b0.w), 0.f);
        v1.x = fmaxf(fmaf(dn, a1.x, b2v.x), 0.f);
        v1.y = fmaxf(fmaf(dn, a1.y, b2v.y), 0.f);
        v1.z = fmaxf(fmaf(dn, a1.z, b2v.z), 0.f);
        v1.w = fmaxf(fmaf(dn, a1.w, b2v.w), 0.f);
        // 8 consecutive elements starting at i0 = node*64 + c8*8
        uint32_t i0 = (uint32_t)node * HID + c8 * 8;
        uint32_t mb = g_mask[i0 >> 5] >> (i0 & 31);
        v0.x = (mb & 1)        ? v0.x * 2.0f : 0.f;
        v0.y = ((mb >> 1) & 1) ? v0.y * 2.0f : 0.f;
        v0.z = ((mb >> 2) & 1) ? v0.z * 2.0f : 0.f;
        v0.w = ((mb >> 3) & 1) ? v0.w * 2.0f : 0.f;
        v1.x = ((mb >> 4) & 1) ? v1.x * 2.0f : 0.f;
        v1.y = ((mb >> 5) & 1) ? v1.y * 2.0f : 0.f;
        v1.z = ((mb >> 6) & 1) ? v1.z * 2.0f : 0.f;
        v1.w = ((mb >> 7) & 1) ? v1.w * 2.0f : 0.f;
        ((float4*)g_h)[(unsigned)(node * 16 + c8 * 2)]     = v0;
        ((float4*)g_h)[(unsigned)(node * 16 + c8 * 2 + 1)] = v1;
    }
}

// ---------------- GEMM2: hs2 = dis .* (h @ W2), fp16 out --------------------
__global__ void k_gemm2(const float* __restrict__ W2) {
    __shared__ float hsm[64][65];
    __shared__ float w2s[64][OUTD];
    const int row0 = blockIdx.x * 64;
    const int t = threadIdx.x;

    for (int idx = t; idx < 64 * 64; idx += 320) {
        int r = idx >> 6, k = idx & 63;
        int gr = row0 + r;
        hsm[r][k] = (gr < NN) ? g_h[(unsigned)(gr * HID + k)] : 0.f;
    }
    for (int idx = t; idx < 64 * OUTD; idx += 320)
        w2s[idx / OUTD][idx % OUTD] = W2[idx];
    __syncthreads();

    int r8 = t / OUTD;
    int c = t % OUTD;
    float acc[8] = {};
#pragma unroll
    for (int k = 0; k < 64; k++) {
        float b = w2s[k][c];
#pragma unroll
        for (int i = 0; i < 8; i++)
            acc[i] = fmaf(hsm[r8 * 8 + i][k], b, acc[i]);
    }
#pragma unroll
    for (int i = 0; i < 8; i++) {
        int row = row0 + r8 * 8 + i;
        if (row < NN) {
            float d = rsqrtf((float)(g_cnt[row] + 1));
            g_hs2h[(unsigned)(row * 64 + c)] = __float2half(d * acc[i]);
        }
    }
}

// ---------------- agg2: warp/node, 10 chunk-lanes x 3 slots, unroll 4 -------
// hs2 row = 64 half padded = 128B = 16 uint2; first 10 uint2 (40 half) used
__global__ void k_agg2(const float* __restrict__ b2, float* __restrict__ out) {
    int node = blockIdx.x * (blockDim.x >> 5) + (threadIdx.x >> 5);
    if (node >= NN) return;
    int lane = threadIdx.x & 31;
    int c = lane % 10;
    int p = (lane < 30) ? (lane / 10) : 3;     // slots 0..2; lanes 30,31 idle
    const uint2* hv = (const uint2*)g_hs2h;    // row stride 16 uint2; use first 10

    int deg = g_cnt[node];
    const unsigned short* sl = g_slot + (unsigned)node * CAP;

    float4 acc = make_float4(0.f, 0.f, 0.f, 0.f);
    if (lane < 10) {   // self-loop
        uint2 r = hv[(unsigned)(node * 16 + c)];
        float2 f0 = __half22float2(*(__half2*)&r.x);
        float2 f1 = __half22float2(*(__half2*)&r.y);
        acc.x = f0.x; acc.y = f0.y; acc.z = f1.x; acc.w = f1.y;
    }

#define A2_STEP(KK) {                                           \
        int s_ = sl[KK];                                        \
        uint2 v_ = hv[(unsigned)(s_ * 16 + c)];                 \
        float2 f0_ = __half22float2(*(__half2*)&v_.x);          \
        float2 f1_ = __half22float2(*(__half2*)&v_.y);          \
        acc.x += f0_.x; acc.y += f0_.y;                         \
        acc.z += f1_.x; acc.w += f1_.y; }

    if (p < 3) {
        int k = p;
        for (; k + 9 < deg; k += 12) {   // 4 rows in flight per slot x 3 slots
            A2_STEP(k) A2_STEP(k + 3) A2_STEP(k + 6) A2_STEP(k + 9)
        }
        for (; k < deg; k += 3) A2_STEP(k)
    }
#undef A2_STEP

    float rx = acc.x + __shfl_down_sync(0xFFFFFFFFu, acc.x, 10) + __shfl_down_sync(0xFFFFFFFFu, acc.x, 20);
    float ry = acc.y + __shfl_down_sync(0xFFFFFFFFu, acc.y, 10) + __shfl_down_sync(0xFFFFFFFFu, acc.y, 20);
    float rz = acc.z + __shfl_down_sync(0xFFFFFFFFu, acc.z, 10) + __shfl_down_sync(0xFFFFFFFFu, acc.z, 20);
    float rw = acc.w + __shfl_down_sync(0xFFFFFFFFu, acc.w, 10) + __shfl_down_sync(0xFFFFFFFFu, acc.w, 20);

    float4 v = make_float4(-CUDART_INF_F, -CUDART_INF_F, -CUDART_INF_F, -CUDART_INF_F);
    if (lane < 10) {
        float d = rsqrtf((float)(deg + 1));
        float4 bb = ((const float4*)b2)[c];
        v.x = fmaf(d, rx, bb.x);
        v.y = fmaf(d, ry, bb.y);
        v.z = fmaf(d, rz, bb.z);
        v.w = fmaf(d, rw, bb.w);
    }
    float m = fmaxf(fmaxf(v.x, v.y), fmaxf(v.z, v.w));
#pragma unroll
    for (int o = 16; o; o >>= 1) m = fmaxf(m, __shfl_xor_sync(0xFFFFFFFFu, m, o));
    float s = 0.f;
    if (lane < 10)
        s = expf(v.x - m) + expf(v.y - m) + expf(v.z - m) + expf(v.w - m);
#pragma unroll
    for (int o = 16; o; o >>= 1) s += __shfl_xor_sync(0xFFFFFFFFu, s, o);
    float lse = m + logf(s);

    if (lane < 10) {
        float4 o4 = make_float4(v.x - lse, v.y - lse, v.z - lse, v.w - lse);
        ((float4*)out)[(unsigned)(node * 10 + c)] = o4;
    }
}

// ---------------- launch -----------------------------------------------------
extern "C" void kernel_launch(void* const* d_in, const int* in_sizes, int n_in,
                              void* d_out, int out_size) {
    const float* x  = (const float*)d_in[0];
    const int*   ei = (const int*)d_in[1];     // [2, NE] row-major
    const float* W1 = (const float*)d_in[2];
    const float* b1 = (const float*)d_in[3];
    const float* W2 = (const float*)d_in[4];
    const float* b2 = (const float*)d_in[5];
    float* out = (float*)d_out;
    const int* src = ei;
    const int* dst = ei + NE;

    void* cnt_ptr = nullptr;
    cudaGetSymbolAddress(&cnt_ptr, g_cnt);
    cudaMemsetAsync(cnt_ptr, 0, NN * sizeof(int));

    k_fill_gemm1<<<NBF + NBG + NBM, 256>>>(src, dst, x, W1);  // fill ∥ GEMM1 ∥ mask
    k_agg1<<<(NN * 32 + 255) / 256, 256>>>(b1);
    k_gemm2<<<(NN + 63) / 64, 320>>>(W2);
    k_agg2<<<(NN * 32 + 255) / 256, 256>>>(b2, out);
}

// round 15
// speedup vs baseline: 1.0658x; 1.0182x over previous
#include <cuda_runtime.h>
#include <cuda_fp16.h>
#include <cstdint>
#include <math_constants.h>

#define NN 50000
#define NE 800000
#define IND 512
#define HID 64
#define OUTD 40
#define CAP 96    // max degree slots per node; Poisson(16) -> P(>96) ~ 0

#define NBF 782   // fill blocks: NE/4/256 rounded up
#define NBG 391   // gemm1 blocks: NN/128 rounded up
#define NMASK ((NN * HID) / 32)   // 100000 mask words
#define NBM 391   // mask blocks: NMASK/256 rounded up

// ---------------- scratch (static device arrays; no allocation) -------------
__device__ int            g_cnt[NN];
__device__ unsigned short g_slot[(size_t)NN * CAP];          // src ids per dst node
__device__ uint32_t       g_mask[NMASK];                     // dropout keep bits
__device__ __align__(16) __half g_hs1h[(size_t)NN * HID];    // raw (x@W1), fp16
__device__ __align__(16) float  g_h[(size_t)NN * HID];       // post relu+dropout
__device__ __align__(16) __half g_hs2h[(size_t)NN * 64];     // d*(h@W2), fp16, padded 64/row

__device__ __forceinline__ __half2 u2h(uint32_t u) { return *reinterpret_cast<__half2*>(&u); }
__device__ __forceinline__ uint32_t h2u(__half2 h) { return *reinterpret_cast<uint32_t*>(&h); }

// ---------------- threefry2x32 (JAX partitionable), key (0, 42) -------------
__device__ __forceinline__ uint32_t rotl32(uint32_t x, int r) {
    return (x << r) | (x >> (32 - r));
}

__device__ __forceinline__ uint32_t tf_bits(uint32_t i) {
    uint32_t x0 = 0u, x1 = i;
    const uint32_t k0 = 0u, k1 = 42u, k2 = 0x1BD11BDAu ^ 42u;
    x0 += k0; x1 += k1;
#define TF_ROUND(r) { x0 += x1; x1 = rotl32(x1, r); x1 ^= x0; }
    TF_ROUND(13) TF_ROUND(15) TF_ROUND(26) TF_ROUND(6)
    x0 += k1; x1 += k2 + 1u;
    TF_ROUND(17) TF_ROUND(29) TF_ROUND(16) TF_ROUND(24)
    x0 += k2; x1 += k0 + 2u;
    TF_ROUND(13) TF_ROUND(15) TF_ROUND(26) TF_ROUND(6)
    x0 += k0; x1 += k1 + 3u;
    TF_ROUND(17) TF_ROUND(29) TF_ROUND(16) TF_ROUND(24)
    x0 += k1; x1 += k2 + 4u;
    TF_ROUND(13) TF_ROUND(15) TF_ROUND(26) TF_ROUND(6)
    x0 += k2; x1 += k0 + 5u;
#undef TF_ROUND
    return x0 ^ x1;
}

// ---------------- GEMM1 helpers (TF32 tensor cores) --------------------------
__device__ __forceinline__ uint32_t f2tf32(float f) {
    uint32_t r;
    asm("cvt.rna.tf32.f32 %0, %1;" : "=r"(r) : "f"(f));
    return r;
}

__device__ __forceinline__ void mma_tf32(float* c, const uint32_t* a, const uint32_t* b) {
    asm volatile(
        "mma.sync.aligned.m16n8k8.row.col.f32.tf32.tf32.f32 "
        "{%0,%1,%2,%3}, {%4,%5,%6,%7}, {%8,%9}, {%0,%1,%2,%3};"
        : "+f"(c[0]), "+f"(c[1]), "+f"(c[2]), "+f"(c[3])
        : "r"(a[0]), "r"(a[1]), "r"(a[2]), "r"(a[3]), "r"(b[0]), "r"(b[1]));
}

#define XPAD 36
#define WPAD 72

// ------- fused: slot fill (< NBF) ∥ GEMM1 (< NBF+NBG) ∥ dropout mask (rest) --
__global__ __launch_bounds__(256) void k_fill_gemm1(const int* __restrict__ src,
                                                    const int* __restrict__ dst,
                                                    const float* __restrict__ x,
                                                    const float* __restrict__ W1) {
    __shared__ uint32_t xs[128][XPAD];
    __shared__ uint32_t ws[32][WPAD];

    if (blockIdx.x < NBF) {   // ---- direct slot fill ----
        int i = (blockIdx.x * 256 + threadIdx.x) * 4;
        if (i < NE) {
            int4 s4 = *(const int4*)(src + i);
            int4 d4 = *(const int4*)(dst + i);
            int p0 = atomicAdd(&g_cnt[d4.x], 1);
            int p1 = atomicAdd(&g_cnt[d4.y], 1);
            int p2 = atomicAdd(&g_cnt[d4.z], 1);
            int p3 = atomicAdd(&g_cnt[d4.w], 1);
            if (p0 < CAP) g_slot[(size_t)d4.x * CAP + p0] = (unsigned short)s4.x;
            if (p1 < CAP) g_slot[(size_t)d4.y * CAP + p1] = (unsigned short)s4.y;
            if (p2 < CAP) g_slot[(size_t)d4.z * CAP + p2] = (unsigned short)s4.z;
            if (p3 < CAP) g_slot[(size_t)d4.w * CAP + p3] = (unsigned short)s4.w;
        }
        return;
    }

    if (blockIdx.x >= NBF + NBG) {   // ---- dropout mask gen (pure ALU) ----
        int j = (blockIdx.x - NBF - NBG) * 256 + threadIdx.x;
        if (j < NMASK) {
            uint32_t base = (uint32_t)j << 5;
            uint32_t w = 0;
#pragma unroll 8
            for (int b = 0; b < 32; b++)
                w |= ((tf_bits(base + b) >> 31) ^ 1u) << b;   // keep iff MSB==0
            g_mask[j] = w;
        }
        return;
    }

    // ---- GEMM1 path: hs1 = x @ W1 (raw), register prefetch on x ----
    const int row0 = (blockIdx.x - NBF) * 128;
    const int t = threadIdx.x;
    const int wid = t >> 5, lane = t & 31;
    const int wm = wid >> 1, wn = wid & 1;
    const int g = lane >> 2, tig = lane & 3;

    int xr_r[4], xr_q[4];
    bool xr_ok[4];
#pragma unroll
    for (int i = 0; i < 4; i++) {
        int f = t + 256 * i;
        xr_r[i] = f >> 3;
        xr_q[i] = (f & 7) << 2;
        xr_ok[i] = (row0 + xr_r[i]) < NN;
    }

    float4 xr[4];
#pragma unroll
    for (int i = 0; i < 4; i++) {
        xr[i] = make_float4(0.f, 0.f, 0.f, 0.f);
        if (xr_ok[i]) xr[i] = *(const float4*)(x + (size_t)(row0 + xr_r[i]) * IND + xr_q[i]);
    }

    float acc[2][4][4] = {};

    for (int kb = 0; kb < IND; kb += 32) {
#pragma unroll
        for (int i = 0; i < 4; i++) {
            int r = xr_r[i], q = xr_q[i];
            xs[r][q]     = f2tf32(xr[i].x);
            xs[r][q + 1] = f2tf32(xr[i].y);
            xs[r][q + 2] = f2tf32(xr[i].z);
            xs[r][q + 3] = f2tf32(xr[i].w);
        }
#pragma unroll
        for (int i = 0; i < 2; i++) {
            int f = t + 256 * i;
            int kk = f >> 4, c4 = (f & 15) << 2;
            float4 v = *(const float4*)(W1 + (size_t)(kb + kk) * HID + c4);
            ws[kk][c4]     = f2tf32(v.x);
            ws[kk][c4 + 1] = f2tf32(v.y);
            ws[kk][c4 + 2] = f2tf32(v.z);
            ws[kk][c4 + 3] = f2tf32(v.w);
        }
        __syncthreads();

        if (kb + 32 < IND) {
#pragma unroll
            for (int i = 0; i < 4; i++)
                if (xr_ok[i])
                    xr[i] = *(const float4*)(x + (size_t)(row0 + xr_r[i]) * IND + (kb + 32) + xr_q[i]);
        }

#pragma unroll
        for (int k8 = 0; k8 < 4; k8++) {
            int k0 = k8 * 8;
            uint32_t a[2][4], b[4][2];
#pragma unroll
            for (int i = 0; i < 2; i++) {
                int rb = wm * 32 + i * 16;
                a[i][0] = xs[rb + g][k0 + tig];
                a[i][1] = xs[rb + g + 8][k0 + tig];
                a[i][2] = xs[rb + g][k0 + tig + 4];
                a[i][3] = xs[rb + g + 8][k0 + tig + 4];
            }
#pragma unroll
            for (int j = 0; j < 4; j++) {
                int nb = wn * 32 + j * 8 + g;
                b[j][0] = ws[k0 + tig][nb];
                b[j][1] = ws[k0 + tig + 4][nb];
            }
#pragma unroll
            for (int i = 0; i < 2; i++)
#pragma unroll
                for (int j = 0; j < 4; j++)
                    mma_tf32(acc[i][j], a[i], b[j]);
        }
        __syncthreads();
    }

    // epilogue: store fp16 (adjacent col pairs -> one half2)
#pragma unroll
    for (int i = 0; i < 2; i++) {
        int r_lo = row0 + wm * 32 + i * 16 + g;
        int r_hi = r_lo + 8;
#pragma unroll
        for (int j = 0; j < 4; j++) {
            int c = wn * 32 + j * 8 + 2 * tig;
            if (r_lo < NN)
                *(__half2*)(g_hs1h + (unsigned)(r_lo * HID + c)) =
                    __floats2half2_rn(acc[i][j][0], acc[i][j][1]);
            if (r_hi < NN)
                *(__half2*)(g_hs1h + (unsigned)(r_hi * HID + c)) =
                    __floats2half2_rn(acc[i][j][2], acc[i][j][3]);
        }
    }
}

// ---------------- agg1: warp/node, 8 chunk-lanes x 4 slots, HFMA2 -----------
// hs1 row = 64 half = 128B = 8 uint4; dropout applied at write via g_mask
__global__ void k_agg1(const float* __restrict__ b1) {
    int node = blockIdx.x * (blockDim.x >> 5) + (threadIdx.x >> 5);
    if (node >= NN) return;
    int lane = threadIdx.x & 31;
    int c8 = lane & 7, p = lane >> 3;           // chunk, slot
    const uint4* hv = (const uint4*)g_hs1h;     // row stride 8 uint4

    int deg = g_cnt[node];
    float dn = rsqrtf((float)(deg + 1));
    const unsigned short* sl = g_slot + (unsigned)node * CAP;

    __half2 acc[4];
#pragma unroll
    for (int j = 0; j < 4; j++) acc[j] = __float2half2_rn(0.f);
    if (p == 0) {   // self-loop: dn * ht[node]
        uint4 r = hv[(unsigned)(node * 8 + c8)];
        __half2 d2 = __float2half2_rn(dn);
        acc[0] = __hmul2(u2h(r.x), d2);
        acc[1] = __hmul2(u2h(r.y), d2);
        acc[2] = __hmul2(u2h(r.z), d2);
        acc[3] = __hmul2(u2h(r.w), d2);
    }

#define A1_STEP(KK) {                                                    \
        int s_ = sl[KK];                                                 \
        float w_ = rsqrtf((float)(__ldg(&g_cnt[s_]) + 1));               \
        __half2 w2_ = __float2half2_rn(w_);                              \
        uint4 v_ = hv[(unsigned)(s_ * 8 + c8)];                          \
        acc[0] = __hfma2(u2h(v_.x), w2_, acc[0]);                        \
        acc[1] = __hfma2(u2h(v_.y), w2_, acc[1]);                        \
        acc[2] = __hfma2(u2h(v_.z), w2_, acc[2]);                        \
        acc[3] = __hfma2(u2h(v_.w), w2_, acc[3]); }

    int k = p;
    for (; k + 8 < deg; k += 12) {   // 3 rows in flight per slot x 4 slots
        A1_STEP(k) A1_STEP(k + 4) A1_STEP(k + 8)
    }
    for (; k < deg; k += 4) A1_STEP(k)
#undef A1_STEP

    // combine 4 slots -> lanes 0..7 (half2 adds via shfl)
#pragma unroll
    for (int j = 0; j < 4; j++) {
        uint32_t o = __shfl_down_sync(0xFFFFFFFFu, h2u(acc[j]), 16);
        acc[j] = __hadd2(acc[j], u2h(o));
    }
#pragma unroll
    for (int j = 0; j < 4; j++) {
        uint32_t o = __shfl_down_sync(0xFFFFFFFFu, h2u(acc[j]), 8);
        acc[j] = __hadd2(acc[j], u2h(o));
    }

    if (p == 0) {   // lanes 0..7: bias + relu + dropout (mask bits), store fp32
        float2 f0 = __half22float2(acc[0]);
        float2 f1 = __half22float2(acc[1]);
        float2 f2 = __half22float2(acc[2]);
        float2 f3 = __half22float2(acc[3]);
        float4 b0 = ((const float4*)b1)[c8 * 2];
        float4 b2v = ((const float4*)b1)[c8 * 2 + 1];
        float4 v0, v1;
        v0.x = fmaxf(fmaf(dn, f0.x, b0.x), 0.f);
        v0.y = fmaxf(fmaf(dn, f0.y, b0.y), 0.f);
        v0.z = fmaxf(fmaf(dn, f1.x, b0.z), 0.f);
        v0.w = fmaxf(fmaf(dn, f1.y, b0.w), 0.f);
        v1.x = fmaxf(fmaf(dn, f2.x, b2v.x), 0.f);
        v1.y = fmaxf(fmaf(dn, f2.y, b2v.y), 0.f);
        v1.z = fmaxf(fmaf(dn, f3.x, b2v.z), 0.f);
        v1.w = fmaxf(fmaf(dn, f3.y, b2v.w), 0.f);
        uint32_t i0 = (uint32_t)node * HID + c8 * 8;
        uint32_t mb = g_mask[i0 >> 5] >> (i0 & 31);
        v0.x = (mb & 1)        ? v0.x * 2.0f : 0.f;
        v0.y = ((mb >> 1) & 1) ? v0.y * 2.0f : 0.f;
        v0.z = ((mb >> 2) & 1) ? v0.z * 2.0f : 0.f;
        v0.w = ((mb >> 3) & 1) ? v0.w * 2.0f : 0.f;
        v1.x = ((mb >> 4) & 1) ? v1.x * 2.0f : 0.f;
        v1.y = ((mb >> 5) & 1) ? v1.y * 2.0f : 0.f;
        v1.z = ((mb >> 6) & 1) ? v1.z * 2.0f : 0.f;
        v1.w = ((mb >> 7) & 1) ? v1.w * 2.0f : 0.f;
        ((float4*)g_h)[(unsigned)(node * 16 + c8 * 2)]     = v0;
        ((float4*)g_h)[(unsigned)(node * 16 + c8 * 2 + 1)] = v1;
    }
}

// ---------------- GEMM2: hs2 = dis .* (h @ W2), fp16 out --------------------
__global__ void k_gemm2(const float* __restrict__ W2) {
    __shared__ float hsm[64][65];
    __shared__ float w2s[64][OUTD];
    const int row0 = blockIdx.x * 64;
    const int t = threadIdx.x;

    for (int idx = t; idx < 64 * 64; idx += 320) {
        int r = idx >> 6, k = idx & 63;
        int gr = row0 + r;
        hsm[r][k] = (gr < NN) ? g_h[(unsigned)(gr * HID + k)] : 0.f;
    }
    for (int idx = t; idx < 64 * OUTD; idx += 320)
        w2s[idx / OUTD][idx % OUTD] = W2[idx];
    __syncthreads();

    int r8 = t / OUTD;
    int c = t % OUTD;
    float acc[8] = {};
#pragma unroll
    for (int k = 0; k < 64; k++) {
        float b = w2s[k][c];
#pragma unroll
        for (int i = 0; i < 8; i++)
            acc[i] = fmaf(hsm[r8 * 8 + i][k], b, acc[i]);
    }
#pragma unroll
    for (int i = 0; i < 8; i++) {
        int row = row0 + r8 * 8 + i;
        if (row < NN) {
            float d = rsqrtf((float)(g_cnt[row] + 1));
            g_hs2h[(unsigned)(row * 64 + c)] = __float2half(d * acc[i]);
        }
    }
}

// ---------------- agg2: warp/node, 5 uint4-chunk-lanes x 6 slots, HADD2 -----
// hs2 row = 64 half padded = 128B = 8 uint4; first 5 uint4 (40 half) used
__global__ void k_agg2(const float* __restrict__ b2, float* __restrict__ out) {
    int node = blockIdx.x * (blockDim.x >> 5) + (threadIdx.x >> 5);
    if (node >= NN) return;
    int lane = threadIdx.x & 31;
    int c5 = lane % 5;
    int p = lane / 5;                          // slots 0..5; lanes 30,31 -> p=6 idle
    const uint4* hv = (const uint4*)g_hs2h;    // row stride 8 uint4; use first 5

    int deg = g_cnt[node];
    const unsigned short* sl = g_slot + (unsigned)node * CAP;

    __half2 acc[4];
#pragma unroll
    for (int j = 0; j < 4; j++) acc[j] = __float2half2_rn(0.f);
    if (lane < 5) {   // self-loop
        uint4 r = hv[(unsigned)(node * 8 + c5)];
        acc[0] = u2h(r.x); acc[1] = u2h(r.y); acc[2] = u2h(r.z); acc[3] = u2h(r.w);
    }

#define A2_STEP(KK) {                                           \
        int s_ = sl[KK];                                        \
        uint4 v_ = hv[(unsigned)(s_ * 8 + c5)];                 \
        acc[0] = __hadd2(acc[0], u2h(v_.x));                    \
        acc[1] = __hadd2(acc[1], u2h(v_.y));                    \
        acc[2] = __hadd2(acc[2], u2h(v_.z));                    \
        acc[3] = __hadd2(acc[3], u2h(v_.w)); }

    if (p < 6) {
        int k = p;
        for (; k + 6 < deg; k += 12) {   // 2 rows in flight per slot x 6 slots
            A2_STEP(k) A2_STEP(k + 6)
        }
        if (k < deg) A2_STEP(k)
    }
#undef A2_STEP

    // combine 6 slots -> lanes 0..4: p+=3 (shfl 15), then p+1,p+2 (shfl 5,10)
#pragma unroll
    for (int j = 0; j < 4; j++) {
        uint32_t o = __shfl_down_sync(0xFFFFFFFFu, h2u(acc[j]), 15);
        if (p < 3) acc[j] = __hadd2(acc[j], u2h(o));
    }
#pragma unroll
    for (int j = 0; j < 4; j++) {
        uint32_t o1 = __shfl_down_sync(0xFFFFFFFFu, h2u(acc[j]), 5);
        uint32_t o2 = __shfl_down_sync(0xFFFFFFFFu, h2u(acc[j]), 10);
        acc[j] = __hadd2(__hadd2(acc[j], u2h(o1)), u2h(o2));
    }

    // lanes 0..4 hold 8 cols each (cols c5*8 .. c5*8+7)
    float v[8];
    float m = -CUDART_INF_F;
    if (lane < 5) {
        float d = rsqrtf((float)(deg + 1));
        float2 f0 = __half22float2(acc[0]);
        float2 f1 = __half22float2(acc[1]);
        float2 f2 = __half22float2(acc[2]);
        float2 f3 = __half22float2(acc[3]);
        float4 ba = ((const float4*)b2)[c5 * 2];
        float4 bb = ((const float4*)b2)[c5 * 2 + 1];
        v[0] = fmaf(d, f0.x, ba.x); v[1] = fmaf(d, f0.y, ba.y);
        v[2] = fmaf(d, f1.x, ba.z); v[3] = fmaf(d, f1.y, ba.w);
        v[4] = fmaf(d, f2.x, bb.x); v[5] = fmaf(d, f2.y, bb.y);
        v[6] = fmaf(d, f3.x, bb.z); v[7] = fmaf(d, f3.y, bb.w);
#pragma unroll
        for (int i = 0; i < 8; i++) m = fmaxf(m, v[i]);
    }
#pragma unroll
    for (int o = 16; o; o >>= 1) m = fmaxf(m, __shfl_xor_sync(0xFFFFFFFFu, m, o));
    float s = 0.f;
    if (lane < 5) {
#pragma unroll
        for (int i = 0; i < 8; i++) s += expf(v[i] - m);
    }
#pragma unroll
    for (int o = 16; o; o >>= 1) s += __shfl_xor_sync(0xFFFFFFFFu, s, o);
    float lse = m + logf(s);

    if (lane < 5) {
        float* op = out + (unsigned)(node * OUTD + c5 * 8);
        *(float4*)op       = make_float4(v[0] - lse, v[1] - lse, v[2] - lse, v[3] - lse);
        *(float4*)(op + 4) = make_float4(v[4] - lse, v[5] - lse, v[6] - lse, v[7] - lse);
    }
}

// ---------------- launch -----------------------------------------------------
extern "C" void kernel_launch(void* const* d_in, const int* in_sizes, int n_in,
                              void* d_out, int out_size) {
    const float* x  = (const float*)d_in[0];
    const int*   ei = (const int*)d_in[1];     // [2, NE] row-major
    const float* W1 = (const float*)d_in[2];
    const float* b1 = (const float*)d_in[3];
    const float* W2 = (const float*)d_in[4];
    const float* b2 = (const float*)d_in[5];
    float* out = (float*)d_out;
    const int* src = ei;
    const int* dst = ei + NE;

    void* cnt_ptr = nullptr;
    cudaGetSymbolAddress(&cnt_ptr, g_cnt);
    cudaMemsetAsync(cnt_ptr, 0, NN * sizeof(int));

    k_fill_gemm1<<<NBF + NBG + NBM, 256>>>(src, dst, x, W1);  // fill ∥ GEMM1 ∥ mask
    k_agg1<<<(NN * 32 + 255) / 256, 256>>>(b1);
    k_gemm2<<<(NN + 63) / 64, 320>>>(W2);
    k_agg2<<<(NN * 32 + 255) / 256, 256>>>(b2, out);
}

// round 16
// speedup vs baseline: 1.1406x; 1.0702x over previous
#include <cuda_runtime.h>
#include <cuda_fp16.h>
#include <cstdint>
#include <math_constants.h>

#define NN 50000
#define NE 800000
#define IND 512
#define HID 64
#define OUTD 40
#define CAP 96    // max degree slots per node; Poisson(16) -> P(>96) ~ 0

#define NBF 782   // fill blocks: NE/4/256 rounded up
#define NBG 391   // gemm1 blocks: NN/128 rounded up
#define NMASK ((NN * HID) / 32)   // 100000 mask words

// ---------------- scratch (static device arrays; no allocation) -------------
__device__ int            g_cnt[NN];
__device__ unsigned short g_slot[(size_t)NN * CAP];          // src ids per dst node
__device__ uint32_t       g_mask[NMASK];                     // dropout keep bits
__device__ __align__(16) __half g_hs1h[(size_t)NN * HID];    // raw (x@W1), fp16
__device__ __align__(16) float  g_h[(size_t)NN * HID];       // post relu+dropout
__device__ __align__(16) __half g_hs2h[(size_t)NN * 64];     // d*(h@W2), fp16, padded 64/row

__device__ __forceinline__ __half2 u2h(uint32_t u) { return *reinterpret_cast<__half2*>(&u); }
__device__ __forceinline__ uint32_t h2u(__half2 h) { return *reinterpret_cast<uint32_t*>(&h); }

// ---------------- threefry2x32 (JAX partitionable), key (0, 42) -------------
__device__ __forceinline__ uint32_t rotl32(uint32_t x, int r) {
    return (x << r) | (x >> (32 - r));
}

__device__ __forceinline__ uint32_t tf_bits(uint32_t i) {
    uint32_t x0 = 0u, x1 = i;
    const uint32_t k0 = 0u, k1 = 42u, k2 = 0x1BD11BDAu ^ 42u;
    x0 += k0; x1 += k1;
#define TF_ROUND(r) { x0 += x1; x1 = rotl32(x1, r); x1 ^= x0; }
    TF_ROUND(13) TF_ROUND(15) TF_ROUND(26) TF_ROUND(6)
    x0 += k1; x1 += k2 + 1u;
    TF_ROUND(17) TF_ROUND(29) TF_ROUND(16) TF_ROUND(24)
    x0 += k2; x1 += k0 + 2u;
    TF_ROUND(13) TF_ROUND(15) TF_ROUND(26) TF_ROUND(6)
    x0 += k0; x1 += k1 + 3u;
    TF_ROUND(17) TF_ROUND(29) TF_ROUND(16) TF_ROUND(24)
    x0 += k1; x1 += k2 + 4u;
    TF_ROUND(13) TF_ROUND(15) TF_ROUND(26) TF_ROUND(6)
    x0 += k2; x1 += k0 + 5u;
#undef TF_ROUND
    return x0 ^ x1;
}

// ---------------- GEMM1 helpers (TF32 tensor cores) --------------------------
__device__ __forceinline__ uint32_t f2tf32(float f) {
    uint32_t r;
    asm("cvt.rna.tf32.f32 %0, %1;" : "=r"(r) : "f"(f));
    return r;
}

__device__ __forceinline__ void mma_tf32(float* c, const uint32_t* a, const uint32_t* b) {
    asm volatile(
        "mma.sync.aligned.m16n8k8.row.col.f32.tf32.tf32.f32 "
        "{%0,%1,%2,%3}, {%4,%5,%6,%7}, {%8,%9}, {%0,%1,%2,%3};"
        : "+f"(c[0]), "+f"(c[1]), "+f"(c[2]), "+f"(c[3])
        : "r"(a[0]), "r"(a[1]), "r"(a[2]), "r"(a[3]), "r"(b[0]), "r"(b[1]));
}

#define XPAD 36
#define WPAD 72

// ------- fused: slot fill + dropout mask (blocks < NBF)  ∥  GEMM1 (rest) ----
__global__ __launch_bounds__(256) void k_fill_gemm1(const int* __restrict__ src,
                                                    const int* __restrict__ dst,
                                                    const float* __restrict__ x,
                                                    const float* __restrict__ W1) {
    __shared__ uint32_t xs[128][XPAD];
    __shared__ uint32_t ws[32][WPAD];

    if (blockIdx.x < NBF) {   // ---- slot fill + mask gen (fill is issue-idle) ----
        int gtid = blockIdx.x * 256 + threadIdx.x;
        int i = gtid * 4;
        if (i < NE) {
            int4 s4 = *(const int4*)(src + i);
            int4 d4 = *(const int4*)(dst + i);
            int p0 = atomicAdd(&g_cnt[d4.x], 1);
            int p1 = atomicAdd(&g_cnt[d4.y], 1);
            int p2 = atomicAdd(&g_cnt[d4.z], 1);
            int p3 = atomicAdd(&g_cnt[d4.w], 1);
            if (p0 < CAP) g_slot[(size_t)d4.x * CAP + p0] = (unsigned short)s4.x;
            if (p1 < CAP) g_slot[(size_t)d4.y * CAP + p1] = (unsigned short)s4.y;
            if (p2 < CAP) g_slot[(size_t)d4.z * CAP + p2] = (unsigned short)s4.z;
            if (p3 < CAP) g_slot[(size_t)d4.w * CAP + p3] = (unsigned short)s4.w;
        }
        if (gtid < NMASK) {   // hash hides behind atomic latency
            uint32_t base = (uint32_t)gtid << 5;
            uint32_t w = 0;
#pragma unroll 8
            for (int b = 0; b < 32; b++)
                w |= ((tf_bits(base + b) >> 31) ^ 1u) << b;   // keep iff MSB==0
            g_mask[gtid] = w;
        }
        return;
    }

    // ---- GEMM1 path: hs1 = x @ W1 (raw), register prefetch on x ----
    const int row0 = (blockIdx.x - NBF) * 128;
    const int t = threadIdx.x;
    const int wid = t >> 5, lane = t & 31;
    const int wm = wid >> 1, wn = wid & 1;
    const int g = lane >> 2, tig = lane & 3;

    int xr_r[4], xr_q[4];
    bool xr_ok[4];
#pragma unroll
    for (int i = 0; i < 4; i++) {
        int f = t + 256 * i;
        xr_r[i] = f >> 3;
        xr_q[i] = (f & 7) << 2;
        xr_ok[i] = (row0 + xr_r[i]) < NN;
    }

    float4 xr[4];
#pragma unroll
    for (int i = 0; i < 4; i++) {
        xr[i] = make_float4(0.f, 0.f, 0.f, 0.f);
        if (xr_ok[i]) xr[i] = *(const float4*)(x + (size_t)(row0 + xr_r[i]) * IND + xr_q[i]);
    }

    float acc[2][4][4] = {};

    for (int kb = 0; kb < IND; kb += 32) {
#pragma unroll
        for (int i = 0; i < 4; i++) {
            int r = xr_r[i], q = xr_q[i];
            xs[r][q]     = f2tf32(xr[i].x);
            xs[r][q + 1] = f2tf32(xr[i].y);
            xs[r][q + 2] = f2tf32(xr[i].z);
            xs[r][q + 3] = f2tf32(xr[i].w);
        }
#pragma unroll
        for (int i = 0; i < 2; i++) {
            int f = t + 256 * i;
            int kk = f >> 4, c4 = (f & 15) << 2;
            float4 v = *(const float4*)(W1 + (size_t)(kb + kk) * HID + c4);
            ws[kk][c4]     = f2tf32(v.x);
            ws[kk][c4 + 1] = f2tf32(v.y);
            ws[kk][c4 + 2] = f2tf32(v.z);
            ws[kk][c4 + 3] = f2tf32(v.w);
        }
        __syncthreads();

        if (kb + 32 < IND) {
#pragma unroll
            for (int i = 0; i < 4; i++)
                if (xr_ok[i])
                    xr[i] = *(const float4*)(x + (size_t)(row0 + xr_r[i]) * IND + (kb + 32) + xr_q[i]);
        }

#pragma unroll
        for (int k8 = 0; k8 < 4; k8++) {
            int k0 = k8 * 8;
            uint32_t a[2][4], b[4][2];
#pragma unroll
            for (int i = 0; i < 2; i++) {
                int rb = wm * 32 + i * 16;
                a[i][0] = xs[rb + g][k0 + tig];
                a[i][1] = xs[rb + g + 8][k0 + tig];
                a[i][2] = xs[rb + g][k0 + tig + 4];
                a[i][3] = xs[rb + g + 8][k0 + tig + 4];
            }
#pragma unroll
            for (int j = 0; j < 4; j++) {
                int nb = wn * 32 + j * 8 + g;
                b[j][0] = ws[k0 + tig][nb];
                b[j][1] = ws[k0 + tig + 4][nb];
            }
#pragma unroll
            for (int i = 0; i < 2; i++)
#pragma unroll
                for (int j = 0; j < 4; j++)
                    mma_tf32(acc[i][j], a[i], b[j]);
        }
        __syncthreads();
    }

    // epilogue: store fp16 (adjacent col pairs -> one half2)
#pragma unroll
    for (int i = 0; i < 2; i++) {
        int r_lo = row0 + wm * 32 + i * 16 + g;
        int r_hi = r_lo + 8;
#pragma unroll
        for (int j = 0; j < 4; j++) {
            int c = wn * 32 + j * 8 + 2 * tig;
            if (r_lo < NN)
                *(__half2*)(g_hs1h + (unsigned)(r_lo * HID + c)) =
                    __floats2half2_rn(acc[i][j][0], acc[i][j][1]);
            if (r_hi < NN)
                *(__half2*)(g_hs1h + (unsigned)(r_hi * HID + c)) =
                    __floats2half2_rn(acc[i][j][2], acc[i][j][3]);
        }
    }
}

// ---------------- agg1: warp/node, 8 chunk-lanes x 4 slots, HFMA2 -----------
// hs1 row = 64 half = 128B = 8 uint4; dropout applied at write via g_mask
__global__ void k_agg1(const float* __restrict__ b1) {
    int node = blockIdx.x * (blockDim.x >> 5) + (threadIdx.x >> 5);
    if (node >= NN) return;
    int lane = threadIdx.x & 31;
    int c8 = lane & 7, p = lane >> 3;           // chunk, slot
    const uint4* hv = (const uint4*)g_hs1h;     // row stride 8 uint4

    int deg = g_cnt[node];
    float dn = rsqrtf((float)(deg + 1));
    const unsigned short* sl = g_slot + (unsigned)node * CAP;

    __half2 acc[4];
#pragma unroll
    for (int j = 0; j < 4; j++) acc[j] = __float2half2_rn(0.f);
    if (p == 0) {   // self-loop: dn * ht[node]
        uint4 r = hv[(unsigned)(node * 8 + c8)];
        __half2 d2 = __float2half2_rn(dn);
        acc[0] = __hmul2(u2h(r.x), d2);
        acc[1] = __hmul2(u2h(r.y), d2);
        acc[2] = __hmul2(u2h(r.z), d2);
        acc[3] = __hmul2(u2h(r.w), d2);
    }

#define A1_STEP(KK) {                                                    \
        int s_ = sl[KK];                                                 \
        float w_ = rsqrtf((float)(__ldg(&g_cnt[s_]) + 1));               \
        __half2 w2_ = __float2half2_rn(w_);                              \
        uint4 v_ = hv[(unsigned)(s_ * 8 + c8)];                          \
        acc[0] = __hfma2(u2h(v_.x), w2_, acc[0]);                        \
        acc[1] = __hfma2(u2h(v_.y), w2_, acc[1]);                        \
        acc[2] = __hfma2(u2h(v_.z), w2_, acc[2]);                        \
        acc[3] = __hfma2(u2h(v_.w), w2_, acc[3]); }

    int k = p;
    for (; k + 8 < deg; k += 12) {   // 3 rows in flight per slot x 4 slots
        A1_STEP(k) A1_STEP(k + 4) A1_STEP(k + 8)
    }
    for (; k < deg; k += 4) A1_STEP(k)
#undef A1_STEP

    // combine 4 slots -> lanes 0..7 (half2 adds via shfl)
#pragma unroll
    for (int j = 0; j < 4; j++) {
        uint32_t o = __shfl_down_sync(0xFFFFFFFFu, h2u(acc[j]), 16);
        acc[j] = __hadd2(acc[j], u2h(o));
    }
#pragma unroll
    for (int j = 0; j < 4; j++) {
        uint32_t o = __shfl_down_sync(0xFFFFFFFFu, h2u(acc[j]), 8);
        acc[j] = __hadd2(acc[j], u2h(o));
    }

    if (p == 0) {   // lanes 0..7: bias + relu + dropout (mask bits), store fp32
        float2 f0 = __half22float2(acc[0]);
        float2 f1 = __half22float2(acc[1]);
        float2 f2 = __half22float2(acc[2]);
        float2 f3 = __half22float2(acc[3]);
        float4 b0 = ((const float4*)b1)[c8 * 2];
        float4 b2v = ((const float4*)b1)[c8 * 2 + 1];
        float4 v0, v1;
        v0.x = fmaxf(fmaf(dn, f0.x, b0.x), 0.f);
        v0.y = fmaxf(fmaf(dn, f0.y, b0.y), 0.f);
        v0.z = fmaxf(fmaf(dn, f1.x, b0.z), 0.f);
        v0.w = fmaxf(fmaf(dn, f1.y, b0.w), 0.f);
        v1.x = fmaxf(fmaf(dn, f2.x, b2v.x), 0.f);
        v1.y = fmaxf(fmaf(dn, f2.y, b2v.y), 0.f);
        v1.z = fmaxf(fmaf(dn, f3.x, b2v.z), 0.f);
        v1.w = fmaxf(fmaf(dn, f3.y, b2v.w), 0.f);
        uint32_t i0 = (uint32_t)node * HID + c8 * 8;
        uint32_t mb = g_mask[i0 >> 5] >> (i0 & 31);
        v0.x = (mb & 1)        ? v0.x * 2.0f : 0.f;
        v0.y = ((mb >> 1) & 1) ? v0.y * 2.0f : 0.f;
        v0.z = ((mb >> 2) & 1) ? v0.z * 2.0f : 0.f;
        v0.w = ((mb >> 3) & 1) ? v0.w * 2.0f : 0.f;
        v1.x = ((mb >> 4) & 1) ? v1.x * 2.0f : 0.f;
        v1.y = ((mb >> 5) & 1) ? v1.y * 2.0f : 0.f;
        v1.z = ((mb >> 6) & 1) ? v1.z * 2.0f : 0.f;
        v1.w = ((mb >> 7) & 1) ? v1.w * 2.0f : 0.f;
        ((float4*)g_h)[(unsigned)(node * 16 + c8 * 2)]     = v0;
        ((float4*)g_h)[(unsigned)(node * 16 + c8 * 2 + 1)] = v1;
    }
}

// ---------------- GEMM2: hs2 = dis .* (h @ W2), fp16 out --------------------
__global__ void k_gemm2(const float* __restrict__ W2) {
    __shared__ float hsm[64][65];
    __shared__ float w2s[64][OUTD];
    const int row0 = blockIdx.x * 64;
    const int t = threadIdx.x;

    for (int idx = t; idx < 64 * 64; idx += 320) {
        int r = idx >> 6, k = idx & 63;
        int gr = row0 + r;
        hsm[r][k] = (gr < NN) ? g_h[(unsigned)(gr * HID + k)] : 0.f;
    }
    for (int idx = t; idx < 64 * OUTD; idx += 320)
        w2s[idx / OUTD][idx % OUTD] = W2[idx];
    __syncthreads();

    int r8 = t / OUTD;
    int c = t % OUTD;
    float acc[8] = {};
#pragma unroll
    for (int k = 0; k < 64; k++) {
        float b = w2s[k][c];
#pragma unroll
        for (int i = 0; i < 8; i++)
            acc[i] = fmaf(hsm[r8 * 8 + i][k], b, acc[i]);
    }
#pragma unroll
    for (int i = 0; i < 8; i++) {
        int row = row0 + r8 * 8 + i;
        if (row < NN) {
            float d = rsqrtf((float)(g_cnt[row] + 1));
            g_hs2h[(unsigned)(row * 64 + c)] = __float2half(d * acc[i]);
        }
    }
}

// ------- agg2: 2 nodes/warp, 16 lanes/node (5 uint4-chunks x 3 slots) -------
// hs2 row = 64 half padded = 128B = 8 uint4; first 5 uint4 (40 half) used
__global__ void k_agg2(const float* __restrict__ b2, float* __restrict__ out) {
    int warp = blockIdx.x * (blockDim.x >> 5) + (threadIdx.x >> 5);
    int lane = threadIdx.x & 31;
    int half = lane >> 4;          // which node in the warp
    int l16 = lane & 15;
    int node = warp * 2 + half;
    if (node >= NN) return;
    int c5 = l16 % 5;
    int p = l16 / 5;               // slots 0..2; l16==15 -> p=3 idle
    const uint4* hv = (const uint4*)g_hs2h;    // row stride 8 uint4; use first 5

    int deg = g_cnt[node];
    const unsigned short* sl = g_slot + (unsigned)node * CAP;

    __half2 acc[4];
#pragma unroll
    for (int j = 0; j < 4; j++) acc[j] = __float2half2_rn(0.f);
    if (l16 < 5) {   // self-loop
        uint4 r = hv[(unsigned)(node * 8 + c5)];
        acc[0] = u2h(r.x); acc[1] = u2h(r.y); acc[2] = u2h(r.z); acc[3] = u2h(r.w);
    }

#define A2_STEP(KK) {                                           \
        int s_ = sl[KK];                                        \
        uint4 v_ = hv[(unsigned)(s_ * 8 + c5)];                 \
        acc[0] = __hadd2(acc[0], u2h(v_.x));                    \
        acc[1] = __hadd2(acc[1], u2h(v_.y));                    \
        acc[2] = __hadd2(acc[2], u2h(v_.z));                    \
        acc[3] = __hadd2(acc[3], u2h(v_.w)); }

    if (p < 3) {
        int k = p;
        for (; k + 3 < deg; k += 6) {   // 2 rows in flight per slot x 3 slots
            A2_STEP(k) A2_STEP(k + 3)
        }
        if (k < deg) A2_STEP(k)
    }
#undef A2_STEP

    // combine 3 slots -> l16 0..4 (shfl_down 5 & 10 stays within the 16-lane half)
#pragma unroll
    for (int j = 0; j < 4; j++) {
        uint32_t o1 = __shfl_down_sync(0xFFFFFFFFu, h2u(acc[j]), 5);
        uint32_t o2 = __shfl_down_sync(0xFFFFFFFFu, h2u(acc[j]), 10);
        acc[j] = __hadd2(__hadd2(acc[j], u2h(o1)), u2h(o2));
    }

    // l16 0..4 hold 8 cols each (cols c5*8 .. c5*8+7)
    float v[8];
    float m = -CUDART_INF_F;
    if (l16 < 5) {
        float d = rsqrtf((float)(deg + 1));
        float2 f0 = __half22float2(acc[0]);
        float2 f1 = __half22float2(acc[1]);
        float2 f2 = __half22float2(acc[2]);
        float2 f3 = __half22float2(acc[3]);
        float4 ba = ((const float4*)b2)[c5 * 2];
        float4 bb = ((const float4*)b2)[c5 * 2 + 1];
        v[0] = fmaf(d, f0.x, ba.x); v[1] = fmaf(d, f0.y, ba.y);
        v[2] = fmaf(d, f1.x, ba.z); v[3] = fmaf(d, f1.y, ba.w);
        v[4] = fmaf(d, f2.x, bb.x); v[5] = fmaf(d, f2.y, bb.y);
        v[6] = fmaf(d, f3.x, bb.z); v[7] = fmaf(d, f3.y, bb.w);
#pragma unroll
        for (int i = 0; i < 8; i++) m = fmaxf(m, v[i]);
    }
    // xor-reduce within aligned 8-lane subgroup (values live in l16 0..4 of each half)
#pragma unroll
    for (int o = 4; o; o >>= 1) m = fmaxf(m, __shfl_xor_sync(0xFFFFFFFFu, m, o));
    float s = 0.f;
    if (l16 < 5) {
#pragma unroll
        for (int i = 0; i < 8; i++) s += expf(v[i] - m);
    }
#pragma unroll
    for (int o = 4; o; o >>= 1) s += __shfl_xor_sync(0xFFFFFFFFu, s, o);
    float lse = m + logf(s);

    if (l16 < 5) {
        float* op = out + (unsigned)(node * OUTD + c5 * 8);
        *(float4*)op       = make_float4(v[0] - lse, v[1] - lse, v[2] - lse, v[3] - lse);
        *(float4*)(op + 4) = make_float4(v[4] - lse, v[5] - lse, v[6] - lse, v[7] - lse);
    }
}

// ---------------- launch -----------------------------------------------------
extern "C" void kernel_launch(void* const* d_in, const int* in_sizes, int n_in,
                              void* d_out, int out_size) {
    const float* x  = (const float*)d_in[0];
    const int*   ei = (const int*)d_in[1];     // [2, NE] row-major
    const float* W1 = (const float*)d_in[2];
    const float* b1 = (const float*)d_in[3];
    const float* W2 = (const float*)d_in[4];
    const float* b2 = (const float*)d_in[5];
    float* out = (float*)d_out;
    const int* src = ei;
    const int* dst = ei + NE;

    void* cnt_ptr = nullptr;
    cudaGetSymbolAddress(&cnt_ptr, g_cnt);
    cudaMemsetAsync(cnt_ptr, 0, NN * sizeof(int));

    k_fill_gemm1<<<NBF + NBG, 256>>>(src, dst, x, W1);   // (fill+mask) ∥ GEMM1
    k_agg1<<<(NN * 32 + 255) / 256, 256>>>(b1);
    k_gemm2<<<(NN + 63) / 64, 320>>>(W2);
    k_agg2<<<(NN / 2 * 32 + 255) / 256, 256>>>(b2, out); // 2 nodes per warp
}

// round 17
// speedup vs baseline: 1.1821x; 1.0364x over previous
#include <cuda_runtime.h>
#include <cuda_fp16.h>
#include <cstdint>
#include <math_constants.h>

#define NN 50000
#define NE 800000
#define IND 512
#define HID 64
#define OUTD 40
#define CAP 96    // max degree slots per node; Poisson(16) -> P(>96) ~ 0

#define NBF 782   // fill blocks: NE/4/256 rounded up
#define NBG 391   // gemm1 blocks: NN/128 rounded up
#define NMASK ((NN * HID) / 32)   // 100000 mask words

// ---------------- scratch (static device arrays; no allocation) -------------
__device__ int            g_cnt[NN];
__device__ unsigned short g_slot[(size_t)NN * CAP];          // src ids per dst node
__device__ uint32_t       g_mask[NMASK];                     // dropout keep bits
__device__ __align__(16) __half g_hs1h[(size_t)NN * HID];    // raw (x@W1), fp16
__device__ __align__(16) float  g_h[(size_t)NN * HID];       // post relu+dropout
__device__ __align__(16) __half g_hs2h[(size_t)NN * 64];     // d*(h@W2), fp16, padded 64/row

__device__ __forceinline__ __half2 u2h(uint32_t u) { return *reinterpret_cast<__half2*>(&u); }
__device__ __forceinline__ uint32_t h2u(__half2 h) { return *reinterpret_cast<uint32_t*>(&h); }

// ---------------- threefry2x32 (JAX partitionable), key (0, 42) -------------
__device__ __forceinline__ uint32_t rotl32(uint32_t x, int r) {
    return (x << r) | (x >> (32 - r));
}

__device__ __forceinline__ uint32_t tf_bits(uint32_t i) {
    uint32_t x0 = 0u, x1 = i;
    const uint32_t k0 = 0u, k1 = 42u, k2 = 0x1BD11BDAu ^ 42u;
    x0 += k0; x1 += k1;
#define TF_ROUND(r) { x0 += x1; x1 = rotl32(x1, r); x1 ^= x0; }
    TF_ROUND(13) TF_ROUND(15) TF_ROUND(26) TF_ROUND(6)
    x0 += k1; x1 += k2 + 1u;
    TF_ROUND(17) TF_ROUND(29) TF_ROUND(16) TF_ROUND(24)
    x0 += k2; x1 += k0 + 2u;
    TF_ROUND(13) TF_ROUND(15) TF_ROUND(26) TF_ROUND(6)
    x0 += k0; x1 += k1 + 3u;
    TF_ROUND(17) TF_ROUND(29) TF_ROUND(16) TF_ROUND(24)
    x0 += k1; x1 += k2 + 4u;
    TF_ROUND(13) TF_ROUND(15) TF_ROUND(26) TF_ROUND(6)
    x0 += k2; x1 += k0 + 5u;
#undef TF_ROUND
    return x0 ^ x1;
}

// ---------------- GEMM1 helpers (TF32 tensor cores) --------------------------
__device__ __forceinline__ uint32_t f2tf32(float f) {
    uint32_t r;
    asm("cvt.rna.tf32.f32 %0, %1;" : "=r"(r) : "f"(f));
    return r;
}

__device__ __forceinline__ void mma_tf32(float* c, const uint32_t* a, const uint32_t* b) {
    asm volatile(
        "mma.sync.aligned.m16n8k8.row.col.f32.tf32.tf32.f32 "
        "{%0,%1,%2,%3}, {%4,%5,%6,%7}, {%8,%9}, {%0,%1,%2,%3};"
        : "+f"(c[0]), "+f"(c[1]), "+f"(c[2]), "+f"(c[3])
        : "r"(a[0]), "r"(a[1]), "r"(a[2]), "r"(a[3]), "r"(b[0]), "r"(b[1]));
}

#define XPAD 36
#define WPAD 72

// ------- fused: slot fill + dropout mask (blocks < NBF)  ∥  GEMM1 (rest) ----
__global__ __launch_bounds__(256) void k_fill_gemm1(const int* __restrict__ src,
                                                    const int* __restrict__ dst,
                                                    const float* __restrict__ x,
                                                    const float* __restrict__ W1) {
    __shared__ uint32_t xs[128][XPAD];
    __shared__ uint32_t ws[32][WPAD];

    if (blockIdx.x < NBF) {   // ---- slot fill + mask gen (fill is issue-idle) ----
        int gtid = blockIdx.x * 256 + threadIdx.x;
        int i = gtid * 4;
        if (i < NE) {
            int4 s4 = *(const int4*)(src + i);
            int4 d4 = *(const int4*)(dst + i);
            int p0 = atomicAdd(&g_cnt[d4.x], 1);
            int p1 = atomicAdd(&g_cnt[d4.y], 1);
            int p2 = atomicAdd(&g_cnt[d4.z], 1);
            int p3 = atomicAdd(&g_cnt[d4.w], 1);
            if (p0 < CAP) g_slot[(size_t)d4.x * CAP + p0] = (unsigned short)s4.x;
            if (p1 < CAP) g_slot[(size_t)d4.y * CAP + p1] = (unsigned short)s4.y;
            if (p2 < CAP) g_slot[(size_t)d4.z * CAP + p2] = (unsigned short)s4.z;
            if (p3 < CAP) g_slot[(size_t)d4.w * CAP + p3] = (unsigned short)s4.w;
        }
        if (gtid < NMASK) {   // hash hides behind atomic latency
            uint32_t base = (uint32_t)gtid << 5;
            uint32_t w = 0;
#pragma unroll 8
            for (int b = 0; b < 32; b++)
                w |= ((tf_bits(base + b) >> 31) ^ 1u) << b;   // keep iff MSB==0
            g_mask[gtid] = w;
        }
        return;
    }

    // ---- GEMM1 path: hs1 = x @ W1 (raw), register prefetch on x ----
    const int row0 = (blockIdx.x - NBF) * 128;
    const int t = threadIdx.x;
    const int wid = t >> 5, lane = t & 31;
    const int wm = wid >> 1, wn = wid & 1;
    const int g = lane >> 2, tig = lane & 3;

    int xr_r[4], xr_q[4];
    bool xr_ok[4];
#pragma unroll
    for (int i = 0; i < 4; i++) {
        int f = t + 256 * i;
        xr_r[i] = f >> 3;
        xr_q[i] = (f & 7) << 2;
        xr_ok[i] = (row0 + xr_r[i]) < NN;
    }

    float4 xr[4];
#pragma unroll
    for (int i = 0; i < 4; i++) {
        xr[i] = make_float4(0.f, 0.f, 0.f, 0.f);
        if (xr_ok[i]) xr[i] = *(const float4*)(x + (size_t)(row0 + xr_r[i]) * IND + xr_q[i]);
    }

    float acc[2][4][4] = {};

    for (int kb = 0; kb < IND; kb += 32) {
#pragma unroll
        for (int i = 0; i < 4; i++) {
            int r = xr_r[i], q = xr_q[i];
            xs[r][q]     = f2tf32(xr[i].x);
            xs[r][q + 1] = f2tf32(xr[i].y);
            xs[r][q + 2] = f2tf32(xr[i].z);
            xs[r][q + 3] = f2tf32(xr[i].w);
        }
#pragma unroll
        for (int i = 0; i < 2; i++) {
            int f = t + 256 * i;
            int kk = f >> 4, c4 = (f & 15) << 2;
            float4 v = *(const float4*)(W1 + (size_t)(kb + kk) * HID + c4);
            ws[kk][c4]     = f2tf32(v.x);
            ws[kk][c4 + 1] = f2tf32(v.y);
            ws[kk][c4 + 2] = f2tf32(v.z);
            ws[kk][c4 + 3] = f2tf32(v.w);
        }
        __syncthreads();

        if (kb + 32 < IND) {
#pragma unroll
            for (int i = 0; i < 4; i++)
                if (xr_ok[i])
                    xr[i] = *(const float4*)(x + (size_t)(row0 + xr_r[i]) * IND + (kb + 32) + xr_q[i]);
        }

#pragma unroll
        for (int k8 = 0; k8 < 4; k8++) {
            int k0 = k8 * 8;
            uint32_t a[2][4], b[4][2];
#pragma unroll
            for (int i = 0; i < 2; i++) {
                int rb = wm * 32 + i * 16;
                a[i][0] = xs[rb + g][k0 + tig];
                a[i][1] = xs[rb + g + 8][k0 + tig];
                a[i][2] = xs[rb + g][k0 + tig + 4];
                a[i][3] = xs[rb + g + 8][k0 + tig + 4];
            }
#pragma unroll
            for (int j = 0; j < 4; j++) {
                int nb = wn * 32 + j * 8 + g;
                b[j][0] = ws[k0 + tig][nb];
                b[j][1] = ws[k0 + tig + 4][nb];
            }
#pragma unroll
            for (int i = 0; i < 2; i++)
#pragma unroll
                for (int j = 0; j < 4; j++)
                    mma_tf32(acc[i][j], a[i], b[j]);
        }
        __syncthreads();
    }

    // epilogue: store fp16 (adjacent col pairs -> one half2)
#pragma unroll
    for (int i = 0; i < 2; i++) {
        int r_lo = row0 + wm * 32 + i * 16 + g;
        int r_hi = r_lo + 8;
#pragma unroll
        for (int j = 0; j < 4; j++) {
            int c = wn * 32 + j * 8 + 2 * tig;
            if (r_lo < NN)
                *(__half2*)(g_hs1h + (unsigned)(r_lo * HID + c)) =
                    __floats2half2_rn(acc[i][j][0], acc[i][j][1]);
            if (r_hi < NN)
                *(__half2*)(g_hs1h + (unsigned)(r_hi * HID + c)) =
                    __floats2half2_rn(acc[i][j][2], acc[i][j][3]);
        }
    }
}

// ------- agg1: 2 nodes/warp, 16 lanes/node (8 uint4-chunks x 2 slots) -------
// hs1 row = 64 half = 128B = 8 uint4; dropout applied at write via g_mask
__global__ void k_agg1(const float* __restrict__ b1) {
    int warp = blockIdx.x * (blockDim.x >> 5) + (threadIdx.x >> 5);
    int lane = threadIdx.x & 31;
    int half = lane >> 4;          // which node in the warp
    int l16 = lane & 15;
    int node = warp * 2 + half;
    if (node >= NN) return;
    int c8 = l16 & 7, p = l16 >> 3;             // chunk, slot (0..1)
    const uint4* hv = (const uint4*)g_hs1h;     // row stride 8 uint4

    int deg = g_cnt[node];
    float dn = rsqrtf((float)(deg + 1));
    const unsigned short* sl = g_slot + (unsigned)node * CAP;

    __half2 acc[4];
#pragma unroll
    for (int j = 0; j < 4; j++) acc[j] = __float2half2_rn(0.f);
    if (p == 0) {   // self-loop: dn * ht[node]
        uint4 r = hv[(unsigned)(node * 8 + c8)];
        __half2 d2 = __float2half2_rn(dn);
        acc[0] = __hmul2(u2h(r.x), d2);
        acc[1] = __hmul2(u2h(r.y), d2);
        acc[2] = __hmul2(u2h(r.z), d2);
        acc[3] = __hmul2(u2h(r.w), d2);
    }

#define A1_STEP(KK) {                                                    \
        int s_ = sl[KK];                                                 \
        float w_ = rsqrtf((float)(__ldg(&g_cnt[s_]) + 1));               \
        __half2 w2_ = __float2half2_rn(w_);                              \
        uint4 v_ = hv[(unsigned)(s_ * 8 + c8)];                          \
        acc[0] = __hfma2(u2h(v_.x), w2_, acc[0]);                        \
        acc[1] = __hfma2(u2h(v_.y), w2_, acc[1]);                        \
        acc[2] = __hfma2(u2h(v_.z), w2_, acc[2]);                        \
        acc[3] = __hfma2(u2h(v_.w), w2_, acc[3]); }

    int k = p;
    for (; k + 4 < deg; k += 6) {   // 3 rows in flight per slot x 2 slots
        A1_STEP(k) A1_STEP(k + 2) A1_STEP(k + 4)
    }
    for (; k < deg; k += 2) A1_STEP(k)
#undef A1_STEP

    // combine 2 slots -> l16 0..7 (shfl_down 8 stays within the 16-lane half)
#pragma unroll
    for (int j = 0; j < 4; j++) {
        uint32_t o = __shfl_down_sync(0xFFFFFFFFu, h2u(acc[j]), 8);
        acc[j] = __hadd2(acc[j], u2h(o));
    }

    if (p == 0) {   // l16 0..7: bias + relu + dropout (mask bits), store fp32
        float2 f0 = __half22float2(acc[0]);
        float2 f1 = __half22float2(acc[1]);
        float2 f2 = __half22float2(acc[2]);
        float2 f3 = __half22float2(acc[3]);
        float4 b0 = ((const float4*)b1)[c8 * 2];
        float4 b2v = ((const float4*)b1)[c8 * 2 + 1];
        float4 v0, v1;
        v0.x = fmaxf(fmaf(dn, f0.x, b0.x), 0.f);
        v0.y = fmaxf(fmaf(dn, f0.y, b0.y), 0.f);
        v0.z = fmaxf(fmaf(dn, f1.x, b0.z), 0.f);
        v0.w = fmaxf(fmaf(dn, f1.y, b0.w), 0.f);
        v1.x = fmaxf(fmaf(dn, f2.x, b2v.x), 0.f);
        v1.y = fmaxf(fmaf(dn, f2.y, b2v.y), 0.f);
        v1.z = fmaxf(fmaf(dn, f3.x, b2v.z), 0.f);
        v1.w = fmaxf(fmaf(dn, f3.y, b2v.w), 0.f);
        uint32_t i0 = (uint32_t)node * HID + c8 * 8;
        uint32_t mb = g_mask[i0 >> 5] >> (i0 & 31);
        v0.x = (mb & 1)        ? v0.x * 2.0f : 0.f;
        v0.y = ((mb >> 1) & 1) ? v0.y * 2.0f : 0.f;
        v0.z = ((mb >> 2) & 1) ? v0.z * 2.0f : 0.f;
        v0.w = ((mb >> 3) & 1) ? v0.w * 2.0f : 0.f;
        v1.x = ((mb >> 4) & 1) ? v1.x * 2.0f : 0.f;
        v1.y = ((mb >> 5) & 1) ? v1.y * 2.0f : 0.f;
        v1.z = ((mb >> 6) & 1) ? v1.z * 2.0f : 0.f;
        v1.w = ((mb >> 7) & 1) ? v1.w * 2.0f : 0.f;
        ((float4*)g_h)[(unsigned)(node * 16 + c8 * 2)]     = v0;
        ((float4*)g_h)[(unsigned)(node * 16 + c8 * 2 + 1)] = v1;
    }
}

// ---------------- GEMM2: hs2 = dis .* (h @ W2), fp16 out --------------------
__global__ void k_gemm2(const float* __restrict__ W2) {
    __shared__ float hsm[64][65];
    __shared__ float w2s[64][OUTD];
    const int row0 = blockIdx.x * 64;
    const int t = threadIdx.x;

    for (int idx = t; idx < 64 * 64; idx += 320) {
        int r = idx >> 6, k = idx & 63;
        int gr = row0 + r;
        hsm[r][k] = (gr < NN) ? g_h[(unsigned)(gr * HID + k)] : 0.f;
    }
    for (int idx = t; idx < 64 * OUTD; idx += 320)
        w2s[idx / OUTD][idx % OUTD] = W2[idx];
    __syncthreads();

    int r8 = t / OUTD;
    int c = t % OUTD;
    float acc[8] = {};
#pragma unroll
    for (int k = 0; k < 64; k++) {
        float b = w2s[k][c];
#pragma unroll
        for (int i = 0; i < 8; i++)
            acc[i] = fmaf(hsm[r8 * 8 + i][k], b, acc[i]);
    }
#pragma unroll
    for (int i = 0; i < 8; i++) {
        int row = row0 + r8 * 8 + i;
        if (row < NN) {
            float d = rsqrtf((float)(g_cnt[row] + 1));
            g_hs2h[(unsigned)(row * 64 + c)] = __float2half(d * acc[i]);
        }
    }
}

// ------- agg2: 2 nodes/warp, 16 lanes/node (5 uint4-chunks x 3 slots) -------
// hs2 row = 64 half padded = 128B = 8 uint4; first 5 uint4 (40 half) used
__global__ void k_agg2(const float* __restrict__ b2, float* __restrict__ out) {
    int warp = blockIdx.x * (blockDim.x >> 5) + (threadIdx.x >> 5);
    int lane = threadIdx.x & 31;
    int half = lane >> 4;          // which node in the warp
    int l16 = lane & 15;
    int node = warp * 2 + half;
    if (node >= NN) return;
    int c5 = l16 % 5;
    int p = l16 / 5;               // slots 0..2; l16==15 -> p=3 idle
    const uint4* hv = (const uint4*)g_hs2h;    // row stride 8 uint4; use first 5

    int deg = g_cnt[node];
    const unsigned short* sl = g_slot + (unsigned)node * CAP;

    __half2 acc[4];
#pragma unroll
    for (int j = 0; j < 4; j++) acc[j] = __float2half2_rn(0.f);
    if (l16 < 5) {   // self-loop
        uint4 r = hv[(unsigned)(node * 8 + c5)];
        acc[0] = u2h(r.x); acc[1] = u2h(r.y); acc[2] = u2h(r.z); acc[3] = u2h(r.w);
    }

#define A2_STEP(KK) {                                           \
        int s_ = sl[KK];                                        \
        uint4 v_ = hv[(unsigned)(s_ * 8 + c5)];                 \
        acc[0] = __hadd2(acc[0], u2h(v_.x));                    \
        acc[1] = __hadd2(acc[1], u2h(v_.y));                    \
        acc[2] = __hadd2(acc[2], u2h(v_.z));                    \
        acc[3] = __hadd2(acc[3], u2h(v_.w)); }

    if (p < 3) {
        int k = p;
        for (; k + 3 < deg; k += 6) {   // 2 rows in flight per slot x 3 slots
            A2_STEP(k) A2_STEP(k + 3)
        }
        if (k < deg) A2_STEP(k)
    }
#undef A2_STEP

    // combine 3 slots -> l16 0..4 (shfl_down 5 & 10 stays within the 16-lane half)
#pragma unroll
    for (int j = 0; j < 4; j++) {
        uint32_t o1 = __shfl_down_sync(0xFFFFFFFFu, h2u(acc[j]), 5);
        uint32_t o2 = __shfl_down_sync(0xFFFFFFFFu, h2u(acc[j]), 10);
        acc[j] = __hadd2(__hadd2(acc[j], u2h(o1)), u2h(o2));
    }

    // l16 0..4 hold 8 cols each (cols c5*8 .. c5*8+7)
    float v[8];
    float m = -CUDART_INF_F;
    if (l16 < 5) {
        float d = rsqrtf((float)(deg + 1));
        float2 f0 = __half22float2(acc[0]);
        float2 f1 = __half22float2(acc[1]);
        float2 f2 = __half22float2(acc[2]);
        float2 f3 = __half22float2(acc[3]);
        float4 ba = ((const float4*)b2)[c5 * 2];
        float4 bb = ((const float4*)b2)[c5 * 2 + 1];
        v[0] = fmaf(d, f0.x, ba.x); v[1] = fmaf(d, f0.y, ba.y);
        v[2] = fmaf(d, f1.x, ba.z); v[3] = fmaf(d, f1.y, ba.w);
        v[4] = fmaf(d, f2.x, bb.x); v[5] = fmaf(d, f2.y, bb.y);
        v[6] = fmaf(d, f3.x, bb.z); v[7] = fmaf(d, f3.y, bb.w);
#pragma unroll
        for (int i = 0; i < 8; i++) m = fmaxf(m, v[i]);
    }
    // xor-reduce within aligned 8-lane subgroup (values live in l16 0..4 of each half)
#pragma unroll
    for (int o = 4; o; o >>= 1) m = fmaxf(m, __shfl_xor_sync(0xFFFFFFFFu, m, o));
    float s = 0.f;
    if (l16 < 5) {
#pragma unroll
        for (int i = 0; i < 8; i++) s += expf(v[i] - m);
    }
#pragma unroll
    for (int o = 4; o; o >>= 1) s += __shfl_xor_sync(0xFFFFFFFFu, s, o);
    float lse = m + logf(s);

    if (l16 < 5) {
        float* op = out + (unsigned)(node * OUTD + c5 * 8);
        *(float4*)op       = make_float4(v[0] - lse, v[1] - lse, v[2] - lse, v[3] - lse);
        *(float4*)(op + 4) = make_float4(v[4] - lse, v[5] - lse, v[6] - lse, v[7] - lse);
    }
}

// ---------------- launch -----------------------------------------------------
extern "C" void kernel_launch(void* const* d_in, const int* in_sizes, int n_in,
                              void* d_out, int out_size) {
    const float* x  = (const float*)d_in[0];
    const int*   ei = (const int*)d_in[1];     // [2, NE] row-major
    const float* W1 = (const float*)d_in[2];
    const float* b1 = (const float*)d_in[3];
    const float* W2 = (const float*)d_in[4];
    const float* b2 = (const float*)d_in[5];
    float* out = (float*)d_out;
    const int* src = ei;
    const int* dst = ei + NE;

    void* cnt_ptr = nullptr;
    cudaGetSymbolAddress(&cnt_ptr, g_cnt);
    cudaMemsetAsync(cnt_ptr, 0, NN * sizeof(int));

    k_fill_gemm1<<<NBF + NBG, 256>>>(src, dst, x, W1);   // (fill+mask) ∥ GEMM1
    k_agg1<<<(NN / 2 * 32 + 255) / 256, 256>>>(b1);      // 2 nodes per warp
    k_gemm2<<<(NN + 63) / 64, 320>>>(W2);
    k_agg2<<<(NN / 2 * 32 + 255) / 256, 256>>>(b2, out); // 2 nodes per warp
}